// round 1
// baseline (speedup 1.0000x reference)
#include <cuda_runtime.h>
#include <math.h>

#define NB 8
#define TSEQ 2048
#define DM 512
#define NH 8
#define HD 64
#define MTOT (NB * TSEQ)          // 16384
#define EQKV (3 * DM)             // 1536

#define QT 64
#define KW 320
#define SPITCH 321
#define ATTN_SMEM_FLOATS (64*64 + 64*SPITCH + 64*64 + 64)
#define ATTN_SMEM_BYTES (ATTN_SMEM_FLOATS * 4)   // 115200

// ---------------- scratch (device globals; no allocations allowed) ----------
__device__ float g_qkv[(size_t)MTOT * EQKV];            // raw qkv projection
__device__ float g_Q[(size_t)NB * NH * TSEQ * HD];      // [n,h,t,d] rope'd
__device__ float g_K[(size_t)NB * NH * TSEQ * HD];
__device__ float g_V[(size_t)NB * NH * TSEQ * HD];
__device__ float g_attn[(size_t)MTOT * DM];             // attention out [n,t,D]
__device__ float g_cos[TSEQ * 32];
__device__ float g_sin[TSEQ * 32];

// ---------------- RoPE table (double precision -> f32, matches reference) ---
__global__ void rope_table_kernel() {
    int idx = blockIdx.x * blockDim.x + threadIdx.x;
    if (idx >= TSEQ * 32) return;
    int t = idx >> 5;
    int j = idx & 31;
    double inv = exp(-log(10000.0) * (double)j / 32.0);
    float ang = (float)t * (float)inv;      // f32 rounding matches jnp
    g_cos[idx] = (float)cos((double)ang);
    g_sin[idx] = (float)sin((double)ang);
}

// ---------------- SGEMM: C[M,N] = A[M,K] * B[N,K]^T (+ bias) ---------------
// 128x128 tile, BK=8, 256 threads, 8x8 per-thread micro-tile, double buffered.
template <bool BIAS>
__global__ __launch_bounds__(256, 2)
void sgemm_tn(const float* __restrict__ A, const float* __restrict__ B,
              const float* __restrict__ bias, float* __restrict__ C,
              int K, int N) {
    __shared__ float As[2][8][128];
    __shared__ float Bs[2][8][128];

    const int tid = threadIdx.x;
    const int m0 = blockIdx.y * 128;
    const int n0 = blockIdx.x * 128;
    const int lr = tid >> 1;            // 0..127 (row within tile)
    const int lk = (tid & 1) << 2;      // 0 or 4
    const int ty = tid >> 4;            // 0..15
    const int tx = tid & 15;            // 0..15

    const float* Ag = A + (size_t)(m0 + lr) * K + lk;
    const float* Bg = B + (size_t)(n0 + lr) * K + lk;

    float acc[8][8];
#pragma unroll
    for (int i = 0; i < 8; i++)
#pragma unroll
        for (int j = 0; j < 8; j++) acc[i][j] = 0.f;

    // stage 0
    {
        float4 a4 = *(const float4*)Ag;
        float4 b4 = *(const float4*)Bg;
        As[0][lk + 0][lr] = a4.x; As[0][lk + 1][lr] = a4.y;
        As[0][lk + 2][lr] = a4.z; As[0][lk + 3][lr] = a4.w;
        Bs[0][lk + 0][lr] = b4.x; Bs[0][lk + 1][lr] = b4.y;
        Bs[0][lk + 2][lr] = b4.z; Bs[0][lk + 3][lr] = b4.w;
    }
    __syncthreads();

    const int nk = K >> 3;
    int buf = 0;
    for (int kt = 0; kt < nk; ++kt) {
        float4 na, nb;
        if (kt + 1 < nk) {
            na = *(const float4*)(Ag + (size_t)(kt + 1) * 8);
            nb = *(const float4*)(Bg + (size_t)(kt + 1) * 8);
        }
#pragma unroll
        for (int kk = 0; kk < 8; ++kk) {
            float a[8], b[8];
            *(float4*)&a[0] = *(const float4*)&As[buf][kk][ty * 8];
            *(float4*)&a[4] = *(const float4*)&As[buf][kk][ty * 8 + 4];
            *(float4*)&b[0] = *(const float4*)&Bs[buf][kk][tx * 8];
            *(float4*)&b[4] = *(const float4*)&Bs[buf][kk][tx * 8 + 4];
#pragma unroll
            for (int i = 0; i < 8; i++)
#pragma unroll
                for (int j = 0; j < 8; j++)
                    acc[i][j] += a[i] * b[j];
        }
        if (kt + 1 < nk) {
            int nbuf = buf ^ 1;
            As[nbuf][lk + 0][lr] = na.x; As[nbuf][lk + 1][lr] = na.y;
            As[nbuf][lk + 2][lr] = na.z; As[nbuf][lk + 3][lr] = na.w;
            Bs[nbuf][lk + 0][lr] = nb.x; Bs[nbuf][lk + 1][lr] = nb.y;
            Bs[nbuf][lk + 2][lr] = nb.z; Bs[nbuf][lk + 3][lr] = nb.w;
        }
        __syncthreads();
        buf ^= 1;
    }

#pragma unroll
    for (int i = 0; i < 8; i++) {
        float out0[4], out1[4];
#pragma unroll
        for (int j = 0; j < 4; j++) {
            out0[j] = acc[i][j];
            out1[j] = acc[i][j + 4];
        }
        if (BIAS) {
#pragma unroll
            for (int j = 0; j < 4; j++) {
                out0[j] += bias[n0 + tx * 8 + j];
                out1[j] += bias[n0 + tx * 8 + 4 + j];
            }
        }
        float* cp = C + (size_t)(m0 + ty * 8 + i) * N + n0 + tx * 8;
        *(float4*)cp = make_float4(out0[0], out0[1], out0[2], out0[3]);
        *(float4*)(cp + 4) = make_float4(out1[0], out1[1], out1[2], out1[3]);
    }
}

// ---------------- RoPE + reshape to [n,h,t,d] ------------------------------
__global__ void rope_reshape_kernel() {
    int idx = blockIdx.x * blockDim.x + threadIdx.x;
    const int total = NB * TSEQ * NH * 32;
    if (idx >= total) return;
    int j = idx & 31;
    int h = (idx >> 5) & 7;
    int t = (idx >> 8) & (TSEQ - 1);
    int n = idx >> 19;

    const float* base = g_qkv + (size_t)(n * TSEQ + t) * EQKV;
    float c = g_cos[t * 32 + j];
    float s = g_sin[t * 32 + j];

    float q1 = base[h * HD + j];
    float q2 = base[h * HD + j + 32];
    float k1 = base[DM + h * HD + j];
    float k2 = base[DM + h * HD + j + 32];
    float v1 = base[2 * DM + h * HD + j];
    float v2 = base[2 * DM + h * HD + j + 32];

    size_t o = ((size_t)(n * NH + h) * TSEQ + t) * HD + j;
    g_Q[o]      = q1 * c - q2 * s;
    g_Q[o + 32] = q2 * c + q1 * s;
    g_K[o]      = k1 * c - k2 * s;
    g_K[o + 32] = k2 * c + k1 * s;
    g_V[o]      = v1;
    g_V[o + 32] = v2;
}

// ---------------- banded attention -----------------------------------------
// One block per (n, h, 64-query tile). Keys [q0-128, q0+192) = 320 columns.
__global__ __launch_bounds__(256, 1)
void attn_win_kernel() {
    extern __shared__ float sm[];
    float* sQt  = sm;                       // [d=64][q=64]
    float* sS   = sm + 64 * 64;             // [64][SPITCH]
    float* sKV  = sS + 64 * SPITCH;         // [64][64]
    float* sInv = sKV + 64 * 64;            // [64]

    const int tid = threadIdx.x;
    const int q0 = blockIdx.x * QT;
    const int nh = blockIdx.y;
    const int n = nh >> 3, h = nh & 7;
    const size_t seqbase = (size_t)nh * TSEQ * HD;
    const float* Qp = g_Q + seqbase;
    const float* Kp = g_K + seqbase;
    const float* Vp = g_V + seqbase;

    // load Q tile transposed: sQt[d][r]
    {
        int r = tid >> 2;
        int d0 = (tid & 3) * 16;
        const float* src = Qp + (size_t)(q0 + r) * HD + d0;
#pragma unroll
        for (int u = 0; u < 4; ++u) {
            float4 v = *(const float4*)(src + u * 4);
            int d = d0 + u * 4;
            sQt[(d + 0) * 64 + r] = v.x;
            sQt[(d + 1) * 64 + r] = v.y;
            sQt[(d + 2) * 64 + r] = v.z;
            sQt[(d + 3) * 64 + r] = v.w;
        }
    }

    const int ty = tid >> 4, tx = tid & 15;
    const int ks = q0 - 128;
    const float scale = 0.125f;  // 1/sqrt(64)

    // ---- pass 1: S = Q K^T with band mask ----
    for (int kt = 0; kt < 5; ++kt) {
        __syncthreads();   // also covers sQt load on first iter
        {
            int r = tid >> 2;
            int d0 = (tid & 3) * 16;
            int j = ks + kt * 64 + r;
            if (j >= 0 && j < TSEQ) {
                const float* src = Kp + (size_t)j * HD + d0;
#pragma unroll
                for (int u = 0; u < 4; ++u) {
                    float4 v = *(const float4*)(src + u * 4);
                    int d = d0 + u * 4;
                    sKV[(d + 0) * 64 + r] = v.x;
                    sKV[(d + 1) * 64 + r] = v.y;
                    sKV[(d + 2) * 64 + r] = v.z;
                    sKV[(d + 3) * 64 + r] = v.w;
                }
            } else {
#pragma unroll
                for (int u = 0; u < 16; ++u)
                    sKV[(d0 + u) * 64 + r] = 0.f;
            }
        }
        __syncthreads();

        float acc[4][4];
#pragma unroll
        for (int i = 0; i < 4; i++)
#pragma unroll
            for (int x = 0; x < 4; x++) acc[i][x] = 0.f;

        const int qi0 = ty * 4, kc0 = tx * 4;
#pragma unroll 16
        for (int d = 0; d < 64; ++d) {
            float4 a = *(const float4*)&sQt[d * 64 + qi0];
            float4 b = *(const float4*)&sKV[d * 64 + kc0];
            acc[0][0] += a.x * b.x; acc[0][1] += a.x * b.y; acc[0][2] += a.x * b.z; acc[0][3] += a.x * b.w;
            acc[1][0] += a.y * b.x; acc[1][1] += a.y * b.y; acc[1][2] += a.y * b.z; acc[1][3] += a.y * b.w;
            acc[2][0] += a.z * b.x; acc[2][1] += a.z * b.y; acc[2][2] += a.z * b.z; acc[2][3] += a.z * b.w;
            acc[3][0] += a.w * b.x; acc[3][1] += a.w * b.y; acc[3][2] += a.w * b.z; acc[3][3] += a.w * b.w;
        }
#pragma unroll
        for (int i = 0; i < 4; i++) {
            int qi = q0 + qi0 + i;
#pragma unroll
            for (int x = 0; x < 4; x++) {
                int j = ks + kt * 64 + kc0 + x;
                int dd = j - qi;
                bool ok = (j >= 0) && (j < TSEQ) && (dd >= -127) && (dd <= 128);
                sS[(qi0 + i) * SPITCH + kt * 64 + kc0 + x] =
                    ok ? acc[i][x] * scale : -INFINITY;
            }
        }
    }
    __syncthreads();

    // ---- pass 2: row softmax (4 lanes per row) ----
    {
        int r = tid >> 2;
        int l = tid & 3;
        float mx = -INFINITY;
        for (int j = l; j < KW; j += 4)
            mx = fmaxf(mx, sS[r * SPITCH + j]);
        mx = fmaxf(mx, __shfl_xor_sync(0xffffffffu, mx, 1));
        mx = fmaxf(mx, __shfl_xor_sync(0xffffffffu, mx, 2));
        float sum = 0.f;
        for (int j = l; j < KW; j += 4) {
            float e = expf(sS[r * SPITCH + j] - mx);
            sS[r * SPITCH + j] = e;
            sum += e;
        }
        sum += __shfl_xor_sync(0xffffffffu, sum, 1);
        sum += __shfl_xor_sync(0xffffffffu, sum, 2);
        if (l == 0) sInv[r] = 1.f / sum;
    }

    // ---- pass 3: O = P V ----
    float o[4][4];
#pragma unroll
    for (int i = 0; i < 4; i++)
#pragma unroll
        for (int x = 0; x < 4; x++) o[i][x] = 0.f;

    const int qi0 = ty * 4, dc0 = tx * 4;
    for (int kt = 0; kt < 5; ++kt) {
        __syncthreads();   // first iter: pass2 done; later: sKV reuse safe
        {
            int r = tid >> 2;
            int d0 = (tid & 3) * 16;
            int j = ks + kt * 64 + r;
            if (j >= 0 && j < TSEQ) {
                const float* src = Vp + (size_t)j * HD + d0;
#pragma unroll
                for (int u = 0; u < 4; ++u)
                    *(float4*)&sKV[r * 64 + d0 + u * 4] = *(const float4*)(src + u * 4);
            } else {
                float4 z = make_float4(0.f, 0.f, 0.f, 0.f);
#pragma unroll
                for (int u = 0; u < 4; ++u)
                    *(float4*)&sKV[r * 64 + d0 + u * 4] = z;
            }
        }
        __syncthreads();

#pragma unroll 8
        for (int j = 0; j < 64; ++j) {
            float4 b = *(const float4*)&sKV[j * 64 + dc0];
            float a0 = sS[(qi0 + 0) * SPITCH + kt * 64 + j];
            float a1 = sS[(qi0 + 1) * SPITCH + kt * 64 + j];
            float a2 = sS[(qi0 + 2) * SPITCH + kt * 64 + j];
            float a3 = sS[(qi0 + 3) * SPITCH + kt * 64 + j];
            o[0][0] += a0 * b.x; o[0][1] += a0 * b.y; o[0][2] += a0 * b.z; o[0][3] += a0 * b.w;
            o[1][0] += a1 * b.x; o[1][1] += a1 * b.y; o[1][2] += a1 * b.z; o[1][3] += a1 * b.w;
            o[2][0] += a2 * b.x; o[2][1] += a2 * b.y; o[2][2] += a2 * b.z; o[2][3] += a2 * b.w;
            o[3][0] += a3 * b.x; o[3][1] += a3 * b.y; o[3][2] += a3 * b.z; o[3][3] += a3 * b.w;
        }
    }

#pragma unroll
    for (int i = 0; i < 4; i++) {
        float inv = sInv[qi0 + i];
        float4 v = make_float4(o[i][0] * inv, o[i][1] * inv,
                               o[i][2] * inv, o[i][3] * inv);
        *(float4*)&g_attn[((size_t)(n * TSEQ) + q0 + qi0 + i) * DM + h * HD + dc0] = v;
    }
}

// ---------------- launcher ---------------------------------------------------
extern "C" void kernel_launch(void* const* d_in, const int* in_sizes, int n_in,
                              void* d_out, int out_size) {
    (void)in_sizes; (void)n_in; (void)out_size;
    const float* x    = (const float*)d_in[0];
    const float* Wqkv = (const float*)d_in[1];
    const float* Wout = (const float*)d_in[2];
    const float* bout = (const float*)d_in[3];
    float* out = (float*)d_out;

    float *qkv_ptr = nullptr, *attn_ptr = nullptr;
    cudaGetSymbolAddress((void**)&qkv_ptr, g_qkv);
    cudaGetSymbolAddress((void**)&attn_ptr, g_attn);

    cudaFuncSetAttribute(attn_win_kernel,
                         cudaFuncAttributeMaxDynamicSharedMemorySize,
                         ATTN_SMEM_BYTES);

    rope_table_kernel<<<(TSEQ * 32 + 255) / 256, 256>>>();

    // qkv = x @ Wqkv^T  : [16384,512] x [1536,512]^T
    sgemm_tn<false><<<dim3(EQKV / 128, MTOT / 128), 256>>>(
        x, Wqkv, nullptr, qkv_ptr, DM, EQKV);

    rope_reshape_kernel<<<(NB * TSEQ * NH * 32 + 255) / 256, 256>>>();

    attn_win_kernel<<<dim3(TSEQ / QT, NB * NH), 256, ATTN_SMEM_BYTES>>>();

    // out = attn @ Wout^T + bout : [16384,512] x [512,512]^T
    sgemm_tn<true><<<dim3(DM / 128, MTOT / 128), 256>>>(
        attn_ptr, Wout, bout, out, DM, DM);
}

// round 3
// speedup vs baseline: 1.4960x; 1.4960x over previous
#include <cuda_runtime.h>
#include <cuda_bf16.h>
#include <math.h>
#include <stdint.h>

#define NB 8
#define TSEQ 2048
#define DM 512
#define NH 8
#define HD 64
#define MTOT (NB * TSEQ)          // 16384
#define EQKV (3 * DM)             // 1536
#define GKK 1536                  // concatenated K = 3 * 512

#define QT 64
#define KW 320
#define SPITCH 321
#define ATTN_SMEM_FLOATS (64*64 + 64*SPITCH + 64*64 + 64)
#define ATTN_SMEM_BYTES (ATTN_SMEM_FLOATS * 4)   // 115200

// ---------------- scratch (device globals; no allocations allowed) ----------
__device__ float g_qkv[(size_t)MTOT * EQKV];            // raw qkv projection
__device__ float g_Q[(size_t)NB * NH * TSEQ * HD];      // [n,h,t,d] rope'd
__device__ float g_K[(size_t)NB * NH * TSEQ * HD];
__device__ float g_V[(size_t)NB * NH * TSEQ * HD];
__device__ float g_attn[(size_t)MTOT * DM];             // attention out [n,t,D]
__device__ float g_cos[TSEQ * 32];
__device__ float g_sin[TSEQ * 32];
// K-concatenated bf16 split operands: A-style rows = [hi | lo | hi],
// B-style rows = [hi | hi | lo]   (C = Ah·Bh + Al·Bh + Ah·Bl)
__device__ __nv_bfloat16 g_xcat[(size_t)MTOT * GKK];
__device__ __nv_bfloat16 g_acat[(size_t)MTOT * GKK];
__device__ __nv_bfloat16 g_wqcat[(size_t)EQKV * GKK];
__device__ __nv_bfloat16 g_wocat[(size_t)DM * GKK];

// ---------------- helpers ----------------------------------------------------
__device__ __forceinline__ uint32_t smem_u32(const void* p) {
    uint32_t a;
    asm("{ .reg .u64 t; cvta.to.shared.u64 t, %1; cvt.u32.u64 %0, t; }"
        : "=r"(a) : "l"(p));
    return a;
}

__device__ __forceinline__ void cp16(uint32_t dst, const void* src) {
    asm volatile("cp.async.cg.shared.global [%0], [%1], 16;"
                 :: "r"(dst), "l"(src) : "memory");
}

__device__ __forceinline__ void ldsm4(uint32_t& r0, uint32_t& r1,
                                      uint32_t& r2, uint32_t& r3, uint32_t addr) {
    asm volatile("ldmatrix.sync.aligned.m8n8.x4.shared.b16 {%0,%1,%2,%3}, [%4];"
                 : "=r"(r0), "=r"(r1), "=r"(r2), "=r"(r3) : "r"(addr));
}

__device__ __forceinline__ void mma16816(float* c, const uint32_t* a,
                                         uint32_t b0, uint32_t b1) {
    asm volatile(
        "mma.sync.aligned.m16n8k16.row.col.f32.bf16.bf16.f32 "
        "{%0,%1,%2,%3}, {%4,%5,%6,%7}, {%8,%9}, {%0,%1,%2,%3};"
        : "+f"(c[0]), "+f"(c[1]), "+f"(c[2]), "+f"(c[3])
        : "r"(a[0]), "r"(a[1]), "r"(a[2]), "r"(a[3]), "r"(b0), "r"(b1));
}

// ---------------- bf16 mma.sync GEMM ----------------------------------------
// C[M,N] = A[M,1536] * B[N,1536]^T (+bias). 128x128 tile, BK=32, 256 threads.
// SMEM rows padded to 40 bf16 (80B) -> conflict-free ldmatrix.
#define SROW 40
#define STAGE_BYTES (128 * SROW * 2)   // 10240

template <bool BIAS>
__global__ __launch_bounds__(256)
void gemm_mma(const __nv_bfloat16* __restrict__ A, const __nv_bfloat16* __restrict__ B,
              const float* __restrict__ bias, float* __restrict__ C, int N) {
    __shared__ __nv_bfloat16 sA[2][128 * SROW];
    __shared__ __nv_bfloat16 sB[2][128 * SROW];

    const int tid = threadIdx.x;
    const int lid = tid & 31;
    const int wid = tid >> 5;
    const int wm = wid >> 2;          // 0..1
    const int wn = wid & 3;           // 0..3
    const int m0 = blockIdx.y * 128;
    const int n0 = blockIdx.x * 128;
    const uint32_t sAb = smem_u32(sA);
    const uint32_t sBb = smem_u32(sB);

    float acc[4][4][4];
#pragma unroll
    for (int i = 0; i < 4; i++)
#pragma unroll
        for (int j = 0; j < 4; j++)
#pragma unroll
            for (int q = 0; q < 4; q++) acc[i][j][q] = 0.f;

    // prefetch lambda-ish macro: 512 16B-chunks per operand, 2 per thread each
#define PREFETCH(stage, k0)                                                     \
    {                                                                           \
        _Pragma("unroll")                                                       \
        for (int i = 0; i < 2; ++i) {                                           \
            int u = tid + i * 256;                                              \
            int row = u >> 2, c = u & 3;                                        \
            cp16(sAb + (stage) * STAGE_BYTES + row * 80 + c * 16,               \
                 A + (size_t)(m0 + row) * GKK + (k0) + c * 8);                  \
            cp16(sBb + (stage) * STAGE_BYTES + row * 80 + c * 16,               \
                 B + (size_t)(n0 + row) * GKK + (k0) + c * 8);                  \
        }                                                                       \
        asm volatile("cp.async.commit_group;" ::: "memory");                    \
    }

    const int NKT = GKK / 32;   // 48
    PREFETCH(0, 0);

    for (int kt = 0; kt < NKT; ++kt) {
        if (kt + 1 < NKT) {
            PREFETCH((kt + 1) & 1, (kt + 1) * 32);
            asm volatile("cp.async.wait_group 1;" ::: "memory");
        } else {
            asm volatile("cp.async.wait_group 0;" ::: "memory");
        }
        __syncthreads();

        const uint32_t sa = sAb + (kt & 1) * STAGE_BYTES;
        const uint32_t sb = sBb + (kt & 1) * STAGE_BYTES;

#pragma unroll
        for (int ks = 0; ks < 32; ks += 16) {
            uint32_t a[4][4], b[2][4];
#pragma unroll
            for (int mi = 0; mi < 4; ++mi) {
                int row = wm * 64 + mi * 16 + (lid & 7) + ((lid >> 3) & 1) * 8;
                int ke = ks + ((lid >> 4) << 3);
                ldsm4(a[mi][0], a[mi][1], a[mi][2], a[mi][3],
                      sa + (uint32_t)(row * SROW + ke) * 2);
            }
#pragma unroll
            for (int nb = 0; nb < 2; ++nb) {
                int n = wn * 32 + nb * 16 + (lid & 7) + ((lid >> 4) & 1) * 8;
                int ke = ks + (((lid >> 3) & 1) << 3);
                ldsm4(b[nb][0], b[nb][1], b[nb][2], b[nb][3],
                      sb + (uint32_t)(n * SROW + ke) * 2);
            }
#pragma unroll
            for (int mi = 0; mi < 4; ++mi)
#pragma unroll
                for (int nf = 0; nf < 4; ++nf)
                    mma16816(acc[mi][nf], a[mi],
                             b[nf >> 1][(nf & 1) * 2], b[nf >> 1][(nf & 1) * 2 + 1]);
        }
        __syncthreads();
    }

    // epilogue
    const int r = lid >> 2;
    const int cc = (lid & 3) * 2;
#pragma unroll
    for (int mi = 0; mi < 4; ++mi) {
#pragma unroll
        for (int nf = 0; nf < 4; ++nf) {
            int row = m0 + wm * 64 + mi * 16 + r;
            int col = n0 + wn * 32 + nf * 8 + cc;
            float bx = 0.f, by = 0.f;
            if (BIAS) { bx = bias[col]; by = bias[col + 1]; }
            float2 v0 = make_float2(acc[mi][nf][0] + bx, acc[mi][nf][1] + by);
            float2 v1 = make_float2(acc[mi][nf][2] + bx, acc[mi][nf][3] + by);
            *(float2*)(C + (size_t)row * N + col) = v0;
            *(float2*)(C + (size_t)(row + 8) * N + col) = v1;
        }
    }
#undef PREFETCH
}

// ---------------- fp32 -> concat split --------------------------------------
__device__ __forceinline__ void split1(float x, unsigned short& h, unsigned short& l) {
    __nv_bfloat16 hb = __float2bfloat16(x);
    float r = x - __bfloat162float(hb);
    __nv_bfloat16 lb = __float2bfloat16(r);
    h = *reinterpret_cast<unsigned short*>(&hb);
    l = *reinterpret_cast<unsigned short*>(&lb);
}

// MODE 0: dst row = [hi | lo | hi]   (activation / A operand)
// MODE 1: dst row = [hi | hi | lo]   (weight / B operand)
template <int MODE>
__global__ void split_cat_kernel(const float* __restrict__ src,
                                 __nv_bfloat16* __restrict__ dst, int total4) {
    int i = blockIdx.x * blockDim.x + threadIdx.x;
    if (i >= total4) return;
    int row = i >> 7;          // 128 float4 per 512-float row
    int c4 = i & 127;
    float4 v = ((const float4*)src)[i];
    ushort4 h, l;
    split1(v.x, h.x, l.x);
    split1(v.y, h.y, l.y);
    split1(v.z, h.z, l.z);
    split1(v.w, h.w, l.w);
    __nv_bfloat16* d = dst + (size_t)row * GKK + c4 * 4;
    if (MODE == 0) {
        *(ushort4*)(d)        = h;
        *(ushort4*)(d + 512)  = l;
        *(ushort4*)(d + 1024) = h;
    } else {
        *(ushort4*)(d)        = h;
        *(ushort4*)(d + 512)  = h;
        *(ushort4*)(d + 1024) = l;
    }
}

// ---------------- RoPE table (double precision -> f32, matches reference) ---
__global__ void rope_table_kernel() {
    int idx = blockIdx.x * blockDim.x + threadIdx.x;
    if (idx >= TSEQ * 32) return;
    int t = idx >> 5;
    int j = idx & 31;
    double inv = exp(-log(10000.0) * (double)j / 32.0);
    float ang = (float)t * (float)inv;      // f32 rounding matches jnp
    g_cos[idx] = (float)cos((double)ang);
    g_sin[idx] = (float)sin((double)ang);
}

// ---------------- RoPE + reshape to [n,h,t,d] ------------------------------
__global__ void rope_reshape_kernel() {
    int idx = blockIdx.x * blockDim.x + threadIdx.x;
    const int total = NB * TSEQ * NH * 32;
    if (idx >= total) return;
    int j = idx & 31;
    int h = (idx >> 5) & 7;
    int t = (idx >> 8) & (TSEQ - 1);
    int n = idx >> 19;

    const float* base = g_qkv + (size_t)(n * TSEQ + t) * EQKV;
    float c = g_cos[t * 32 + j];
    float s = g_sin[t * 32 + j];

    float q1 = base[h * HD + j];
    float q2 = base[h * HD + j + 32];
    float k1 = base[DM + h * HD + j];
    float k2 = base[DM + h * HD + j + 32];
    float v1 = base[2 * DM + h * HD + j];
    float v2 = base[2 * DM + h * HD + j + 32];

    size_t o = ((size_t)(n * NH + h) * TSEQ + t) * HD + j;
    g_Q[o]      = q1 * c - q2 * s;
    g_Q[o + 32] = q2 * c + q1 * s;
    g_K[o]      = k1 * c - k2 * s;
    g_K[o + 32] = k2 * c + k1 * s;
    g_V[o]      = v1;
    g_V[o + 32] = v2;
}

// ---------------- banded attention -----------------------------------------
// One block per (n, h, 64-query tile). Keys [q0-128, q0+192) = 320 columns.
__global__ __launch_bounds__(256, 1)
void attn_win_kernel() {
    extern __shared__ float smf[];
    float* sQt  = smf;                      // [d=64][q=64]
    float* sS   = smf + 64 * 64;            // [64][SPITCH]
    float* sKV  = sS + 64 * SPITCH;         // [64][64]
    float* sInv = sKV + 64 * 64;            // [64]

    const int tid = threadIdx.x;
    const int q0 = blockIdx.x * QT;
    const int nh = blockIdx.y;
    const int n = nh >> 3, h = nh & 7;
    const size_t seqbase = (size_t)nh * TSEQ * HD;
    const float* Qp = g_Q + seqbase;
    const float* Kp = g_K + seqbase;
    const float* Vp = g_V + seqbase;

    // load Q tile transposed: sQt[d][r]
    {
        int r = tid >> 2;
        int d0 = (tid & 3) * 16;
        const float* src = Qp + (size_t)(q0 + r) * HD + d0;
#pragma unroll
        for (int u = 0; u < 4; ++u) {
            float4 v = *(const float4*)(src + u * 4);
            int d = d0 + u * 4;
            sQt[(d + 0) * 64 + r] = v.x;
            sQt[(d + 1) * 64 + r] = v.y;
            sQt[(d + 2) * 64 + r] = v.z;
            sQt[(d + 3) * 64 + r] = v.w;
        }
    }

    const int ty = tid >> 4, tx = tid & 15;
    const int ks = q0 - 128;
    const float scale = 0.125f;  // 1/sqrt(64)

    // ---- pass 1: S = Q K^T with band mask ----
    for (int kt = 0; kt < 5; ++kt) {
        __syncthreads();   // also covers sQt load on first iter
        {
            int r = tid >> 2;
            int d0 = (tid & 3) * 16;
            int j = ks + kt * 64 + r;
            if (j >= 0 && j < TSEQ) {
                const float* src = Kp + (size_t)j * HD + d0;
#pragma unroll
                for (int u = 0; u < 4; ++u) {
                    float4 v = *(const float4*)(src + u * 4);
                    int d = d0 + u * 4;
                    sKV[(d + 0) * 64 + r] = v.x;
                    sKV[(d + 1) * 64 + r] = v.y;
                    sKV[(d + 2) * 64 + r] = v.z;
                    sKV[(d + 3) * 64 + r] = v.w;
                }
            } else {
#pragma unroll
                for (int u = 0; u < 16; ++u)
                    sKV[(d0 + u) * 64 + r] = 0.f;
            }
        }
        __syncthreads();

        float acc[4][4];
#pragma unroll
        for (int i = 0; i < 4; i++)
#pragma unroll
            for (int x = 0; x < 4; x++) acc[i][x] = 0.f;

        const int qi0 = ty * 4, kc0 = tx * 4;
#pragma unroll 16
        for (int d = 0; d < 64; ++d) {
            float4 a = *(const float4*)&sQt[d * 64 + qi0];
            float4 b = *(const float4*)&sKV[d * 64 + kc0];
            acc[0][0] += a.x * b.x; acc[0][1] += a.x * b.y; acc[0][2] += a.x * b.z; acc[0][3] += a.x * b.w;
            acc[1][0] += a.y * b.x; acc[1][1] += a.y * b.y; acc[1][2] += a.y * b.z; acc[1][3] += a.y * b.w;
            acc[2][0] += a.z * b.x; acc[2][1] += a.z * b.y; acc[2][2] += a.z * b.z; acc[2][3] += a.z * b.w;
            acc[3][0] += a.w * b.x; acc[3][1] += a.w * b.y; acc[3][2] += a.w * b.z; acc[3][3] += a.w * b.w;
        }
#pragma unroll
        for (int i = 0; i < 4; i++) {
            int qi = q0 + qi0 + i;
#pragma unroll
            for (int x = 0; x < 4; x++) {
                int j = ks + kt * 64 + kc0 + x;
                int dd = j - qi;
                bool ok = (j >= 0) && (j < TSEQ) && (dd >= -127) && (dd <= 128);
                sS[(qi0 + i) * SPITCH + kt * 64 + kc0 + x] =
                    ok ? acc[i][x] * scale : -INFINITY;
            }
        }
    }
    __syncthreads();

    // ---- pass 2: row softmax (4 lanes per row) ----
    {
        int r = tid >> 2;
        int l = tid & 3;
        float mx = -INFINITY;
        for (int j = l; j < KW; j += 4)
            mx = fmaxf(mx, sS[r * SPITCH + j]);
        mx = fmaxf(mx, __shfl_xor_sync(0xffffffffu, mx, 1));
        mx = fmaxf(mx, __shfl_xor_sync(0xffffffffu, mx, 2));
        float sum = 0.f;
        for (int j = l; j < KW; j += 4) {
            float e = expf(sS[r * SPITCH + j] - mx);
            sS[r * SPITCH + j] = e;
            sum += e;
        }
        sum += __shfl_xor_sync(0xffffffffu, sum, 1);
        sum += __shfl_xor_sync(0xffffffffu, sum, 2);
        if (l == 0) sInv[r] = 1.f / sum;
    }

    // ---- pass 3: O = P V ----
    float o[4][4];
#pragma unroll
    for (int i = 0; i < 4; i++)
#pragma unroll
        for (int x = 0; x < 4; x++) o[i][x] = 0.f;

    const int qi0 = ty * 4, dc0 = tx * 4;
    for (int kt = 0; kt < 5; ++kt) {
        __syncthreads();   // first iter: pass2 done; later: sKV reuse safe
        {
            int r = tid >> 2;
            int d0 = (tid & 3) * 16;
            int j = ks + kt * 64 + r;
            if (j >= 0 && j < TSEQ) {
                const float* src = Vp + (size_t)j * HD + d0;
#pragma unroll
                for (int u = 0; u < 4; ++u)
                    *(float4*)&sKV[r * 64 + d0 + u * 4] = *(const float4*)(src + u * 4);
            } else {
                float4 z = make_float4(0.f, 0.f, 0.f, 0.f);
#pragma unroll
                for (int u = 0; u < 4; ++u)
                    *(float4*)&sKV[r * 64 + d0 + u * 4] = z;
            }
        }
        __syncthreads();

#pragma unroll 8
        for (int j = 0; j < 64; ++j) {
            float4 b = *(const float4*)&sKV[j * 64 + dc0];
            float a0 = sS[(qi0 + 0) * SPITCH + kt * 64 + j];
            float a1 = sS[(qi0 + 1) * SPITCH + kt * 64 + j];
            float a2 = sS[(qi0 + 2) * SPITCH + kt * 64 + j];
            float a3 = sS[(qi0 + 3) * SPITCH + kt * 64 + j];
            o[0][0] += a0 * b.x; o[0][1] += a0 * b.y; o[0][2] += a0 * b.z; o[0][3] += a0 * b.w;
            o[1][0] += a1 * b.x; o[1][1] += a1 * b.y; o[1][2] += a1 * b.z; o[1][3] += a1 * b.w;
            o[2][0] += a2 * b.x; o[2][1] += a2 * b.y; o[2][2] += a2 * b.z; o[2][3] += a2 * b.w;
            o[3][0] += a3 * b.x; o[3][1] += a3 * b.y; o[3][2] += a3 * b.z; o[3][3] += a3 * b.w;
        }
    }

#pragma unroll
    for (int i = 0; i < 4; i++) {
        float inv = sInv[qi0 + i];
        float4 v = make_float4(o[i][0] * inv, o[i][1] * inv,
                               o[i][2] * inv, o[i][3] * inv);
        *(float4*)&g_attn[((size_t)(n * TSEQ) + q0 + qi0 + i) * DM + h * HD + dc0] = v;
    }
}

// ---------------- launcher ---------------------------------------------------
extern "C" void kernel_launch(void* const* d_in, const int* in_sizes, int n_in,
                              void* d_out, int out_size) {
    (void)in_sizes; (void)n_in; (void)out_size;
    const float* x    = (const float*)d_in[0];
    const float* Wqkv = (const float*)d_in[1];
    const float* Wout = (const float*)d_in[2];
    const float* bout = (const float*)d_in[3];
    float* out = (float*)d_out;

    float *qkv_ptr = nullptr, *attn_ptr = nullptr;
    cudaGetSymbolAddress((void**)&qkv_ptr, g_qkv);
    cudaGetSymbolAddress((void**)&attn_ptr, g_attn);
    __nv_bfloat16 *xcat, *acat, *wqcat, *wocat;
    cudaGetSymbolAddress((void**)&xcat, g_xcat);
    cudaGetSymbolAddress((void**)&acat, g_acat);
    cudaGetSymbolAddress((void**)&wqcat, g_wqcat);
    cudaGetSymbolAddress((void**)&wocat, g_wocat);

    cudaFuncSetAttribute(attn_win_kernel,
                         cudaFuncAttributeMaxDynamicSharedMemorySize,
                         ATTN_SMEM_BYTES);

    rope_table_kernel<<<(TSEQ * 32 + 255) / 256, 256>>>();

    // splits (MODE 0 for activations, MODE 1 for weights)
    split_cat_kernel<0><<<(MTOT * 128 + 255) / 256, 256>>>(x, xcat, MTOT * 128);
    split_cat_kernel<1><<<(EQKV * 128 + 255) / 256, 256>>>(Wqkv, wqcat, EQKV * 128);
    split_cat_kernel<1><<<(DM * 128 + 255) / 256, 256>>>(Wout, wocat, DM * 128);

    // qkv = x @ Wqkv^T  (split-bf16 HMMA, K=1536)
    gemm_mma<false><<<dim3(EQKV / 128, MTOT / 128), 256>>>(
        xcat, wqcat, nullptr, qkv_ptr, EQKV);

    rope_reshape_kernel<<<(NB * TSEQ * NH * 32 + 255) / 256, 256>>>();

    attn_win_kernel<<<dim3(TSEQ / QT, NB * NH), 256, ATTN_SMEM_BYTES>>>();

    // out = attn @ Wout^T + bout
    split_cat_kernel<0><<<(MTOT * 128 + 255) / 256, 256>>>(attn_ptr, acat, MTOT * 128);
    gemm_mma<true><<<dim3(DM / 128, MTOT / 128), 256>>>(
        acat, wocat, bout, out, DM);
}

// round 4
// speedup vs baseline: 1.6830x; 1.1250x over previous
#include <cuda_runtime.h>
#include <cuda_bf16.h>
#include <math.h>
#include <stdint.h>

#define NB 8
#define TSEQ 2048
#define DM 512
#define NH 8
#define HD 64
#define MTOT (NB * TSEQ)          // 16384
#define EQKV (3 * DM)             // 1536
#define GKK 1536                  // concatenated K = 3 * 512

#define QT 64
#define KW 320
#define SPITCH 321

// attention smem layout (dynamic)
#define AOFF_Q   0                      // 64 x 200 bf16 (Qcat, later Pcat)
#define AOFF_B0  25600                  // 64 x 200 bf16 (K/V tile buf 0)
#define AOFF_B1  51200                  // 64 x 200 bf16 (K/V tile buf 1)
#define AOFF_S   76800                  // 64 x 321 fp32
#define AOFF_INV 158976                 // 64 fp32
#define ATTN2_SMEM 159232

// ---------------- scratch (device globals; no allocations allowed) ----------
__device__ float g_qkv[(size_t)MTOT * EQKV];            // raw qkv projection
__device__ float g_attn[(size_t)MTOT * DM];             // attention out [n,t,D]
__device__ float g_cos[TSEQ * 32];
__device__ float g_sin[TSEQ * 32];
// attention operands (bf16, split-concat)
__device__ __nv_bfloat16 g_Qc[(size_t)NB * NH * TSEQ * 192];  // [Qh|Ql|Qh]
__device__ __nv_bfloat16 g_Kc[(size_t)NB * NH * TSEQ * 192];  // [Kh|Kh|Kl]
__device__ __nv_bfloat16 g_Vth[(size_t)NB * NH * HD * TSEQ];  // V^T hi [d][t]
__device__ __nv_bfloat16 g_Vtl[(size_t)NB * NH * HD * TSEQ];  // V^T lo [d][t]
// GEMM operands (K-concatenated split)
__device__ __nv_bfloat16 g_xcat[(size_t)MTOT * GKK];
__device__ __nv_bfloat16 g_acat[(size_t)MTOT * GKK];
__device__ __nv_bfloat16 g_wqcat[(size_t)EQKV * GKK];
__device__ __nv_bfloat16 g_wocat[(size_t)DM * GKK];

// ---------------- helpers ----------------------------------------------------
__device__ __forceinline__ uint32_t smem_u32(const void* p) {
    uint32_t a;
    asm("{ .reg .u64 t; cvta.to.shared.u64 t, %1; cvt.u32.u64 %0, t; }"
        : "=r"(a) : "l"(p));
    return a;
}

__device__ __forceinline__ void cp16(uint32_t dst, const void* src) {
    asm volatile("cp.async.cg.shared.global [%0], [%1], 16;"
                 :: "r"(dst), "l"(src) : "memory");
}

__device__ __forceinline__ void ldsm4(uint32_t& r0, uint32_t& r1,
                                      uint32_t& r2, uint32_t& r3, uint32_t addr) {
    asm volatile("ldmatrix.sync.aligned.m8n8.x4.shared.b16 {%0,%1,%2,%3}, [%4];"
                 : "=r"(r0), "=r"(r1), "=r"(r2), "=r"(r3) : "r"(addr));
}

__device__ __forceinline__ void mma16816(float* c, const uint32_t* a,
                                         uint32_t b0, uint32_t b1) {
    asm volatile(
        "mma.sync.aligned.m16n8k16.row.col.f32.bf16.bf16.f32 "
        "{%0,%1,%2,%3}, {%4,%5,%6,%7}, {%8,%9}, {%0,%1,%2,%3};"
        : "+f"(c[0]), "+f"(c[1]), "+f"(c[2]), "+f"(c[3])
        : "r"(a[0]), "r"(a[1]), "r"(a[2]), "r"(a[3]), "r"(b0), "r"(b1));
}

__device__ __forceinline__ void split1(float x, __nv_bfloat16& h, __nv_bfloat16& l) {
    h = __float2bfloat16(x);
    l = __float2bfloat16(x - __bfloat162float(h));
}

// ---------------- bf16 mma.sync GEMM ----------------------------------------
#define SROW 40
#define STAGE_BYTES (128 * SROW * 2)   // 10240

template <bool BIAS>
__global__ __launch_bounds__(256)
void gemm_mma(const __nv_bfloat16* __restrict__ A, const __nv_bfloat16* __restrict__ B,
              const float* __restrict__ bias, float* __restrict__ C, int N) {
    __shared__ __nv_bfloat16 sA[2][128 * SROW];
    __shared__ __nv_bfloat16 sB[2][128 * SROW];

    const int tid = threadIdx.x;
    const int lid = tid & 31;
    const int wid = tid >> 5;
    const int wm = wid >> 2;          // 0..1
    const int wn = wid & 3;           // 0..3
    const int m0 = blockIdx.y * 128;
    const int n0 = blockIdx.x * 128;
    const uint32_t sAb = smem_u32(sA);
    const uint32_t sBb = smem_u32(sB);

    float acc[4][4][4];
#pragma unroll
    for (int i = 0; i < 4; i++)
#pragma unroll
        for (int j = 0; j < 4; j++)
#pragma unroll
            for (int q = 0; q < 4; q++) acc[i][j][q] = 0.f;

#define PREFETCH(stage, k0)                                                     \
    {                                                                           \
        _Pragma("unroll")                                                       \
        for (int i = 0; i < 2; ++i) {                                           \
            int u = tid + i * 256;                                              \
            int row = u >> 2, c = u & 3;                                        \
            cp16(sAb + (stage) * STAGE_BYTES + row * 80 + c * 16,               \
                 A + (size_t)(m0 + row) * GKK + (k0) + c * 8);                  \
            cp16(sBb + (stage) * STAGE_BYTES + row * 80 + c * 16,               \
                 B + (size_t)(n0 + row) * GKK + (k0) + c * 8);                  \
        }                                                                       \
        asm volatile("cp.async.commit_group;" ::: "memory");                    \
    }

    const int NKT = GKK / 32;   // 48
    PREFETCH(0, 0);

    for (int kt = 0; kt < NKT; ++kt) {
        if (kt + 1 < NKT) {
            PREFETCH((kt + 1) & 1, (kt + 1) * 32);
            asm volatile("cp.async.wait_group 1;" ::: "memory");
        } else {
            asm volatile("cp.async.wait_group 0;" ::: "memory");
        }
        __syncthreads();

        const uint32_t sa = sAb + (kt & 1) * STAGE_BYTES;
        const uint32_t sb = sBb + (kt & 1) * STAGE_BYTES;

#pragma unroll
        for (int ks = 0; ks < 32; ks += 16) {
            uint32_t a[4][4], b[2][4];
#pragma unroll
            for (int mi = 0; mi < 4; ++mi) {
                int row = wm * 64 + mi * 16 + (lid & 7) + ((lid >> 3) & 1) * 8;
                int ke = ks + ((lid >> 4) << 3);
                ldsm4(a[mi][0], a[mi][1], a[mi][2], a[mi][3],
                      sa + (uint32_t)(row * SROW + ke) * 2);
            }
#pragma unroll
            for (int nb = 0; nb < 2; ++nb) {
                int n = wn * 32 + nb * 16 + (lid & 7) + ((lid >> 4) & 1) * 8;
                int ke = ks + (((lid >> 3) & 1) << 3);
                ldsm4(b[nb][0], b[nb][1], b[nb][2], b[nb][3],
                      sb + (uint32_t)(n * SROW + ke) * 2);
            }
#pragma unroll
            for (int mi = 0; mi < 4; ++mi)
#pragma unroll
                for (int nf = 0; nf < 4; ++nf)
                    mma16816(acc[mi][nf], a[mi],
                             b[nf >> 1][(nf & 1) * 2], b[nf >> 1][(nf & 1) * 2 + 1]);
        }
        __syncthreads();
    }

    const int r = lid >> 2;
    const int cc = (lid & 3) * 2;
#pragma unroll
    for (int mi = 0; mi < 4; ++mi) {
#pragma unroll
        for (int nf = 0; nf < 4; ++nf) {
            int row = m0 + wm * 64 + mi * 16 + r;
            int col = n0 + wn * 32 + nf * 8 + cc;
            float bx = 0.f, by = 0.f;
            if (BIAS) { bx = bias[col]; by = bias[col + 1]; }
            float2 v0 = make_float2(acc[mi][nf][0] + bx, acc[mi][nf][1] + by);
            float2 v1 = make_float2(acc[mi][nf][2] + bx, acc[mi][nf][3] + by);
            *(float2*)(C + (size_t)row * N + col) = v0;
            *(float2*)(C + (size_t)(row + 8) * N + col) = v1;
        }
    }
#undef PREFETCH
}

// ---------------- fp32 -> concat split (GEMM operands) ----------------------
// MODE 0: dst row = [hi | lo | hi]   (activation / A operand)
// MODE 1: dst row = [hi | hi | lo]   (weight / B operand)
template <int MODE>
__global__ void split_cat_kernel(const float* __restrict__ src,
                                 __nv_bfloat16* __restrict__ dst, int total4) {
    int i = blockIdx.x * blockDim.x + threadIdx.x;
    if (i >= total4) return;
    int row = i >> 7;          // 128 float4 per 512-float row
    int c4 = i & 127;
    float4 v = ((const float4*)src)[i];
    __nv_bfloat16 h[4], l[4];
    split1(v.x, h[0], l[0]);
    split1(v.y, h[1], l[1]);
    split1(v.z, h[2], l[2]);
    split1(v.w, h[3], l[3]);
    __nv_bfloat16* d = dst + (size_t)row * GKK + c4 * 4;
    if (MODE == 0) {
        *(uint64_t*)(d)        = *(uint64_t*)h;
        *(uint64_t*)(d + 512)  = *(uint64_t*)l;
        *(uint64_t*)(d + 1024) = *(uint64_t*)h;
    } else {
        *(uint64_t*)(d)        = *(uint64_t*)h;
        *(uint64_t*)(d + 512)  = *(uint64_t*)h;
        *(uint64_t*)(d + 1024) = *(uint64_t*)l;
    }
}

// ---------------- RoPE table ------------------------------------------------
__global__ void rope_table_kernel() {
    int idx = blockIdx.x * blockDim.x + threadIdx.x;
    if (idx >= TSEQ * 32) return;
    int t = idx >> 5;
    int j = idx & 31;
    double inv = exp(-log(10000.0) * (double)j / 32.0);
    float ang = (float)t * (float)inv;
    g_cos[idx] = (float)cos((double)ang);
    g_sin[idx] = (float)sin((double)ang);
}

// ---------------- RoPE + split-concat Q/K to [n,h,t,192] --------------------
__global__ void rope_qk_kernel() {
    int idx = blockIdx.x * blockDim.x + threadIdx.x;
    const int total = NB * TSEQ * NH * 32;
    if (idx >= total) return;
    int j = idx & 31;
    int h = (idx >> 5) & 7;
    int t = (idx >> 8) & (TSEQ - 1);
    int n = idx >> 19;
    int nh = n * NH + h;

    const float* base = g_qkv + (size_t)(n * TSEQ + t) * EQKV;
    float c = g_cos[t * 32 + j];
    float s = g_sin[t * 32 + j];

    float q1 = base[h * HD + j];
    float q2 = base[h * HD + j + 32];
    float k1 = base[DM + h * HD + j];
    float k2 = base[DM + h * HD + j + 32];

    float q1r = q1 * c - q2 * s;
    float q2r = q2 * c + q1 * s;
    float k1r = k1 * c - k2 * s;
    float k2r = k2 * c + k1 * s;

    __nv_bfloat16 h1, l1, h2, l2;
    __nv_bfloat16* qrow = g_Qc + ((size_t)nh * TSEQ + t) * 192;
    split1(q1r, h1, l1); split1(q2r, h2, l2);
    qrow[j]        = h1; qrow[64 + j]  = l1; qrow[128 + j] = h1;
    qrow[32 + j]   = h2; qrow[96 + j]  = l2; qrow[160 + j] = h2;

    __nv_bfloat16* krow = g_Kc + ((size_t)nh * TSEQ + t) * 192;
    split1(k1r, h1, l1); split1(k2r, h2, l2);
    krow[j]        = h1; krow[64 + j]  = h1; krow[128 + j] = l1;
    krow[32 + j]   = h2; krow[96 + j]  = h2; krow[160 + j] = l2;
}

// ---------------- V transpose + split: [n,h,d,t] hi/lo ----------------------
__global__ void vtrans_kernel() {
    __shared__ __nv_bfloat16 svh[64 * 33];
    __shared__ __nv_bfloat16 svl[64 * 33];
    const int tid = threadIdx.x;
    const int nh = blockIdx.y;
    const int n = nh >> 3, h = nh & 7;
    const int t0 = blockIdx.x * 32;

#pragma unroll
    for (int i = 0; i < 8; i++) {
        int e = tid + i * 256;
        int tl = e >> 6, d = e & 63;
        float v = g_qkv[(size_t)(n * TSEQ + t0 + tl) * EQKV + 2 * DM + h * HD + d];
        __nv_bfloat16 hb, lb;
        split1(v, hb, lb);
        svh[d * 33 + tl] = hb;
        svl[d * 33 + tl] = lb;
    }
    __syncthreads();
#pragma unroll
    for (int i = 0; i < 8; i++) {
        int e = tid + i * 256;
        int d = e >> 5, tl = e & 31;
        size_t o = ((size_t)nh * HD + d) * TSEQ + t0 + tl;
        g_Vth[o] = svh[d * 33 + tl];
        g_Vtl[o] = svl[d * 33 + tl];
    }
}

// ---------------- tensor-core banded attention ------------------------------
// CTA per (n*NH+h, 64-q tile). 256 threads = 8 warps (4 q-rows x 2 cols).
__global__ __launch_bounds__(256, 1)
void attn_mma_kernel() {
    extern __shared__ char smc[];
    const uint32_t sb = smem_u32(smc);
    float* sS = (float*)(smc + AOFF_S);
    float* sInv = (float*)(smc + AOFF_INV);
    __nv_bfloat16* sP = (__nv_bfloat16*)(smc);   // reuses Q region in phase C

    const int tid = threadIdx.x;
    const int lid = tid & 31, wid = tid >> 5;
    const int wr = wid & 3, wc = wid >> 2;
    const int q0 = blockIdx.x * QT;
    const int nh = blockIdx.y;
    const int n = nh >> 3, h = nh & 7;
    const int ks = q0 - 128;
    const float scale = 0.125f;

    // ---- load Qcat tile ----
    {
        const __nv_bfloat16* src = g_Qc + ((size_t)nh * TSEQ + q0) * 192;
#pragma unroll
        for (int i = 0; i < 6; i++) {
            int u = tid + i * 256;
            int r = u / 24, c = u % 24;
            cp16(sb + AOFF_Q + r * 400 + c * 16, src + (size_t)r * 192 + c * 8);
        }
    }
    // ---- K tile 0 ----
    {
#pragma unroll
        for (int i = 0; i < 6; i++) {
            int u = tid + i * 256;
            int r = u / 24, c = u % 24;
            int j = ks + r;
            j = j < 0 ? 0 : (j > TSEQ - 1 ? TSEQ - 1 : j);
            cp16(sb + AOFF_B0 + r * 400 + c * 16,
                 g_Kc + ((size_t)nh * TSEQ + j) * 192 + c * 8);
        }
    }
    asm volatile("cp.async.commit_group;" ::: "memory");

    float oacc[4][4];
#pragma unroll
    for (int i = 0; i < 4; i++)
#pragma unroll
        for (int q = 0; q < 4; q++) oacc[i][q] = 0.f;

    // ---- phase 1: S = Qcat · Kcat^T, masked+scaled into sS ----
    for (int jt = 0; jt < 5; ++jt) {
        if (jt < 4) {
            uint32_t dstb = sb + (((jt + 1) & 1) ? AOFF_B1 : AOFF_B0);
#pragma unroll
            for (int i = 0; i < 6; i++) {
                int u = tid + i * 256;
                int r = u / 24, c = u % 24;
                int j = ks + (jt + 1) * 64 + r;
                j = j < 0 ? 0 : (j > TSEQ - 1 ? TSEQ - 1 : j);
                cp16(dstb + r * 400 + c * 16,
                     g_Kc + ((size_t)nh * TSEQ + j) * 192 + c * 8);
            }
            asm volatile("cp.async.commit_group;" ::: "memory");
            asm volatile("cp.async.wait_group 1;" ::: "memory");
        } else {
            asm volatile("cp.async.wait_group 0;" ::: "memory");
        }
        __syncthreads();

        uint32_t bbase = sb + ((jt & 1) ? AOFF_B1 : AOFF_B0);
        float sacc[4][4];
#pragma unroll
        for (int i = 0; i < 4; i++)
#pragma unroll
            for (int q = 0; q < 4; q++) sacc[i][q] = 0.f;

#pragma unroll
        for (int k16 = 0; k16 < 12; ++k16) {
            uint32_t a[4], b[2][4];
            {
                int row = wr * 16 + (lid & 7) + ((lid >> 3) & 1) * 8;
                int ke = k16 * 16 + ((lid >> 4) << 3);
                ldsm4(a[0], a[1], a[2], a[3], sb + AOFF_Q + row * 400 + ke * 2);
            }
#pragma unroll
            for (int nb = 0; nb < 2; ++nb) {
                int nn = wc * 32 + nb * 16 + (lid & 7) + ((lid >> 4) & 1) * 8;
                int ke = k16 * 16 + (((lid >> 3) & 1) << 3);
                ldsm4(b[nb][0], b[nb][1], b[nb][2], b[nb][3],
                      bbase + nn * 400 + ke * 2);
            }
#pragma unroll
            for (int nf = 0; nf < 4; ++nf)
                mma16816(sacc[nf], a, b[nf >> 1][(nf & 1) * 2],
                         b[nf >> 1][(nf & 1) * 2 + 1]);
        }

        // write S with band mask
        int r4 = lid >> 2, cc = (lid & 3) * 2;
#pragma unroll
        for (int nf = 0; nf < 4; ++nf) {
            int col = jt * 64 + wc * 32 + nf * 8 + cc;
            int jg = ks + col;
#pragma unroll
            for (int half = 0; half < 2; ++half) {
                int ql = wr * 16 + r4 + half * 8;
                int qg = q0 + ql;
#pragma unroll
                for (int e = 0; e < 2; ++e) {
                    int j = jg + e;
                    int dd = j - qg;
                    bool ok = (j >= 0) && (j < TSEQ) && (dd >= -127) && (dd <= 128);
                    sS[ql * SPITCH + col + e] =
                        ok ? sacc[nf][half * 2 + e] * scale : -INFINITY;
                }
            }
        }
        __syncthreads();
    }

    // ---- phase 2: softmax (exp in place, inverse sums) ----
    {
        int r = tid >> 2, l = tid & 3;
        float mx = -INFINITY;
        for (int j = l; j < KW; j += 4)
            mx = fmaxf(mx, sS[r * SPITCH + j]);
        mx = fmaxf(mx, __shfl_xor_sync(0xffffffffu, mx, 1));
        mx = fmaxf(mx, __shfl_xor_sync(0xffffffffu, mx, 2));
        float sum = 0.f;
        for (int j = l; j < KW; j += 4) {
            float e = __expf(sS[r * SPITCH + j] - mx);
            sS[r * SPITCH + j] = e;
            sum += e;
        }
        sum += __shfl_xor_sync(0xffffffffu, sum, 1);
        sum += __shfl_xor_sync(0xffffffffu, sum, 2);
        if (l == 0) sInv[r] = 1.f / sum;
    }
    __syncthreads();

#define ISSUE_V(jt_, offb)                                                      \
    {                                                                           \
        _Pragma("unroll")                                                       \
        for (int i = 0; i < 6; i++) {                                           \
            int u = tid + i * 256;                                              \
            int r = u / 24, c = u % 24;                                         \
            int jb = ks + (jt_) * 64 + (c & 7) * 8;                             \
            jb = jb < 0 ? 0 : (jb > TSEQ - 8 ? TSEQ - 8 : jb);                  \
            const __nv_bfloat16* vs =                                           \
                (c < 16 ? (const __nv_bfloat16*)g_Vth                           \
                        : (const __nv_bfloat16*)g_Vtl);                         \
            cp16(sb + (offb) + r * 400 + c * 16,                                \
                 vs + ((size_t)nh * HD + r) * TSEQ + jb);                       \
        }                                                                       \
        asm volatile("cp.async.commit_group;" ::: "memory");                    \
    }

    ISSUE_V(0, AOFF_B0);

    // ---- phase 3: O += Pcat · Vcat^T ----
    for (int jt = 0; jt < 5; ++jt) {
        // P split into sP (cols [Ph|Pl|Ph])
#pragma unroll
        for (int i = 0; i < 16; i++) {
            int e = tid + i * 256;
            int row = e >> 6, c = e & 63;
            float p = sS[row * SPITCH + jt * 64 + c];
            __nv_bfloat16 ph, pl;
            split1(p, ph, pl);
            sP[row * 200 + c] = ph;
            sP[row * 200 + 64 + c] = pl;
            sP[row * 200 + 128 + c] = ph;
        }
        if (jt < 4) {
            ISSUE_V(jt + 1, (((jt + 1) & 1) ? AOFF_B1 : AOFF_B0));
            asm volatile("cp.async.wait_group 1;" ::: "memory");
        } else {
            asm volatile("cp.async.wait_group 0;" ::: "memory");
        }
        __syncthreads();

        uint32_t bbase = sb + ((jt & 1) ? AOFF_B1 : AOFF_B0);
#pragma unroll
        for (int k16 = 0; k16 < 12; ++k16) {
            uint32_t a[4], b[2][4];
            {
                int row = wr * 16 + (lid & 7) + ((lid >> 3) & 1) * 8;
                int ke = k16 * 16 + ((lid >> 4) << 3);
                ldsm4(a[0], a[1], a[2], a[3], sb + AOFF_Q + row * 400 + ke * 2);
            }
#pragma unroll
            for (int nb = 0; nb < 2; ++nb) {
                int nn = wc * 32 + nb * 16 + (lid & 7) + ((lid >> 4) & 1) * 8;
                int ke = k16 * 16 + (((lid >> 3) & 1) << 3);
                ldsm4(b[nb][0], b[nb][1], b[nb][2], b[nb][3],
                      bbase + nn * 400 + ke * 2);
            }
#pragma unroll
            for (int nf = 0; nf < 4; ++nf)
                mma16816(oacc[nf], a, b[nf >> 1][(nf & 1) * 2],
                         b[nf >> 1][(nf & 1) * 2 + 1]);
        }
        __syncthreads();
    }
#undef ISSUE_V

    // ---- phase 4: normalize + write ----
    {
        int r4 = lid >> 2, cc = (lid & 3) * 2;
#pragma unroll
        for (int nf = 0; nf < 4; ++nf) {
            int col = h * HD + wc * 32 + nf * 8 + cc;
            int ql0 = wr * 16 + r4;
            float i0 = sInv[ql0], i8 = sInv[ql0 + 8];
            float2 v0 = make_float2(oacc[nf][0] * i0, oacc[nf][1] * i0);
            float2 v1 = make_float2(oacc[nf][2] * i8, oacc[nf][3] * i8);
            *(float2*)&g_attn[((size_t)(n * TSEQ) + q0 + ql0) * DM + col] = v0;
            *(float2*)&g_attn[((size_t)(n * TSEQ) + q0 + ql0 + 8) * DM + col] = v1;
        }
    }
}

// ---------------- launcher ---------------------------------------------------
extern "C" void kernel_launch(void* const* d_in, const int* in_sizes, int n_in,
                              void* d_out, int out_size) {
    (void)in_sizes; (void)n_in; (void)out_size;
    const float* x    = (const float*)d_in[0];
    const float* Wqkv = (const float*)d_in[1];
    const float* Wout = (const float*)d_in[2];
    const float* bout = (const float*)d_in[3];
    float* out = (float*)d_out;

    float *qkv_ptr = nullptr, *attn_ptr = nullptr;
    cudaGetSymbolAddress((void**)&qkv_ptr, g_qkv);
    cudaGetSymbolAddress((void**)&attn_ptr, g_attn);
    __nv_bfloat16 *xcat, *acat, *wqcat, *wocat;
    cudaGetSymbolAddress((void**)&xcat, g_xcat);
    cudaGetSymbolAddress((void**)&acat, g_acat);
    cudaGetSymbolAddress((void**)&wqcat, g_wqcat);
    cudaGetSymbolAddress((void**)&wocat, g_wocat);

    cudaFuncSetAttribute(attn_mma_kernel,
                         cudaFuncAttributeMaxDynamicSharedMemorySize,
                         ATTN2_SMEM);

    rope_table_kernel<<<(TSEQ * 32 + 255) / 256, 256>>>();

    split_cat_kernel<0><<<(MTOT * 128 + 255) / 256, 256>>>(x, xcat, MTOT * 128);
    split_cat_kernel<1><<<(EQKV * 128 + 255) / 256, 256>>>(Wqkv, wqcat, EQKV * 128);
    split_cat_kernel<1><<<(DM * 128 + 255) / 256, 256>>>(Wout, wocat, DM * 128);

    // qkv = x @ Wqkv^T  (split-bf16 HMMA, K=1536)
    gemm_mma<false><<<dim3(EQKV / 128, MTOT / 128), 256>>>(
        xcat, wqcat, nullptr, qkv_ptr, EQKV);

    rope_qk_kernel<<<(NB * TSEQ * NH * 32 + 255) / 256, 256>>>();
    vtrans_kernel<<<dim3(TSEQ / 32, NB * NH), 256>>>();

    attn_mma_kernel<<<dim3(TSEQ / QT, NB * NH), 256, ATTN2_SMEM>>>();

    // out = attn @ Wout^T + bout
    split_cat_kernel<0><<<(MTOT * 128 + 255) / 256, 256>>>(attn_ptr, acat, MTOT * 128);
    gemm_mma<true><<<dim3(DM / 128, MTOT / 128), 256>>>(
        acat, wocat, bout, out, DM);
}

// round 6
// speedup vs baseline: 2.0491x; 1.2176x over previous
#include <cuda_runtime.h>
#include <cuda_bf16.h>
#include <math.h>
#include <stdint.h>

#define NB 8
#define TSEQ 2048
#define DM 512
#define NH 8
#define HD 64
#define MTOT (NB * TSEQ)          // 16384
#define EQKV (3 * DM)             // 1536
#define GKK 1536                  // concatenated K = 3 * 512

#define QT 64

// ---- flash attention smem layout (bytes) ----
#define AQ_OFF   0                         // 64 x 200 bf16 (Qcat), pitch 400B
#define AK_OFF(s) (25600 + (s) * 43008)    // 64 x 200 bf16 K tile, pitch 400B
#define AV_OFF(s) (AK_OFF(s) + 25600)      // 64 x 136 bf16 V tile (hi|lo), pitch 272B
#define ARMAX_OFF 111616                   // 2 x 64 fp32
#define ASUM_OFF  112128                   // 2 x 64 fp32
#define AO_OFF    25600                    // 64 x 64 fp32 exchange (overlays stage0 K)
#define AFL_SMEM  112640

// ---------------- scratch (device globals) ----------------------------------
__device__ float g_qkv[(size_t)MTOT * EQKV];
__device__ float g_cos[TSEQ * 32];
__device__ float g_sin[TSEQ * 32];
__device__ __nv_bfloat16 g_Qc[(size_t)NB * NH * TSEQ * 192];  // [Qh|Ql|Qh]
__device__ __nv_bfloat16 g_Kc[(size_t)NB * NH * TSEQ * 192];  // [Kh|Kh|Kl]
__device__ __nv_bfloat16 g_Vth[(size_t)NB * NH * HD * TSEQ];  // V^T hi [d][t]
__device__ __nv_bfloat16 g_Vtl[(size_t)NB * NH * HD * TSEQ];  // V^T lo [d][t]
__device__ __nv_bfloat16 g_xcat[(size_t)MTOT * GKK];
__device__ __nv_bfloat16 g_acat[(size_t)MTOT * GKK];          // attention out (split)
__device__ __nv_bfloat16 g_wqcat[(size_t)EQKV * GKK];
__device__ __nv_bfloat16 g_wocat[(size_t)DM * GKK];

// ---------------- helpers ----------------------------------------------------
__device__ __forceinline__ uint32_t smem_u32(const void* p) {
    uint32_t a;
    asm("{ .reg .u64 t; cvta.to.shared.u64 t, %1; cvt.u32.u64 %0, t; }"
        : "=r"(a) : "l"(p));
    return a;
}

__device__ __forceinline__ void cp16(uint32_t dst, const void* src) {
    asm volatile("cp.async.cg.shared.global [%0], [%1], 16;"
                 :: "r"(dst), "l"(src) : "memory");
}

__device__ __forceinline__ void ldsm4(uint32_t& r0, uint32_t& r1,
                                      uint32_t& r2, uint32_t& r3, uint32_t addr) {
    asm volatile("ldmatrix.sync.aligned.m8n8.x4.shared.b16 {%0,%1,%2,%3}, [%4];"
                 : "=r"(r0), "=r"(r1), "=r"(r2), "=r"(r3) : "r"(addr));
}

__device__ __forceinline__ void mma16816(float* c, const uint32_t* a,
                                         uint32_t b0, uint32_t b1) {
    asm volatile(
        "mma.sync.aligned.m16n8k16.row.col.f32.bf16.bf16.f32 "
        "{%0,%1,%2,%3}, {%4,%5,%6,%7}, {%8,%9}, {%0,%1,%2,%3};"
        : "+f"(c[0]), "+f"(c[1]), "+f"(c[2]), "+f"(c[3])
        : "r"(a[0]), "r"(a[1]), "r"(a[2]), "r"(a[3]), "r"(b0), "r"(b1));
}

__device__ __forceinline__ void split1(float x, __nv_bfloat16& h, __nv_bfloat16& l) {
    h = __float2bfloat16(x);
    l = __float2bfloat16(x - __bfloat162float(h));
}

__device__ __forceinline__ uint16_t bfbits(__nv_bfloat16 b) {
    return *reinterpret_cast<uint16_t*>(&b);
}

__device__ __forceinline__ uint32_t pack2(float a, float b) {
    __nv_bfloat16 ha = __float2bfloat16(a), hb = __float2bfloat16(b);
    return (uint32_t)bfbits(ha) | ((uint32_t)bfbits(hb) << 16);
}

// pack the bf16 lo-residuals of a,b
__device__ __forceinline__ uint32_t pack2lo(float a, float b) {
    __nv_bfloat16 ha = __float2bfloat16(a), hb = __float2bfloat16(b);
    __nv_bfloat16 la = __float2bfloat16(a - __bfloat162float(ha));
    __nv_bfloat16 lb = __float2bfloat16(b - __bfloat162float(hb));
    return (uint32_t)bfbits(la) | ((uint32_t)bfbits(lb) << 16);
}

// ---------------- bf16 mma.sync GEMM ----------------------------------------
#define SROW 40
#define STAGE_BYTES (128 * SROW * 2)   // 10240

template <bool BIAS>
__global__ __launch_bounds__(256)
void gemm_mma(const __nv_bfloat16* __restrict__ A, const __nv_bfloat16* __restrict__ B,
              const float* __restrict__ bias, float* __restrict__ C, int N) {
    __shared__ __nv_bfloat16 sA[2][128 * SROW];
    __shared__ __nv_bfloat16 sB[2][128 * SROW];

    const int tid = threadIdx.x;
    const int lid = tid & 31;
    const int wid = tid >> 5;
    const int wm = wid >> 2;
    const int wn = wid & 3;
    const int m0 = blockIdx.y * 128;
    const int n0 = blockIdx.x * 128;
    const uint32_t sAb = smem_u32(sA);
    const uint32_t sBb = smem_u32(sB);

    float acc[4][4][4];
#pragma unroll
    for (int i = 0; i < 4; i++)
#pragma unroll
        for (int j = 0; j < 4; j++)
#pragma unroll
            for (int q = 0; q < 4; q++) acc[i][j][q] = 0.f;

#define PREFETCH(stage, k0)                                                     \
    {                                                                           \
        _Pragma("unroll")                                                       \
        for (int i = 0; i < 2; ++i) {                                           \
            int u = tid + i * 256;                                              \
            int row = u >> 2, c = u & 3;                                        \
            cp16(sAb + (stage) * STAGE_BYTES + row * 80 + c * 16,               \
                 A + (size_t)(m0 + row) * GKK + (k0) + c * 8);                  \
            cp16(sBb + (stage) * STAGE_BYTES + row * 80 + c * 16,               \
                 B + (size_t)(n0 + row) * GKK + (k0) + c * 8);                  \
        }                                                                       \
        asm volatile("cp.async.commit_group;" ::: "memory");                    \
    }

    const int NKT = GKK / 32;   // 48
    PREFETCH(0, 0);

    for (int kt = 0; kt < NKT; ++kt) {
        if (kt + 1 < NKT) {
            PREFETCH((kt + 1) & 1, (kt + 1) * 32);
            asm volatile("cp.async.wait_group 1;" ::: "memory");
        } else {
            asm volatile("cp.async.wait_group 0;" ::: "memory");
        }
        __syncthreads();

        const uint32_t sa = sAb + (kt & 1) * STAGE_BYTES;
        const uint32_t sb = sBb + (kt & 1) * STAGE_BYTES;

#pragma unroll
        for (int ks = 0; ks < 32; ks += 16) {
            uint32_t a[4][4], b[2][4];
#pragma unroll
            for (int mi = 0; mi < 4; ++mi) {
                int row = wm * 64 + mi * 16 + (lid & 7) + ((lid >> 3) & 1) * 8;
                int ke = ks + ((lid >> 4) << 3);
                ldsm4(a[mi][0], a[mi][1], a[mi][2], a[mi][3],
                      sa + (uint32_t)(row * SROW + ke) * 2);
            }
#pragma unroll
            for (int nb = 0; nb < 2; ++nb) {
                int n = wn * 32 + nb * 16 + (lid & 7) + ((lid >> 4) & 1) * 8;
                int ke = ks + (((lid >> 3) & 1) << 3);
                ldsm4(b[nb][0], b[nb][1], b[nb][2], b[nb][3],
                      sb + (uint32_t)(n * SROW + ke) * 2);
            }
#pragma unroll
            for (int mi = 0; mi < 4; ++mi)
#pragma unroll
                for (int nf = 0; nf < 4; ++nf)
                    mma16816(acc[mi][nf], a[mi],
                             b[nf >> 1][(nf & 1) * 2], b[nf >> 1][(nf & 1) * 2 + 1]);
        }
        __syncthreads();
    }

    const int r = lid >> 2;
    const int cc = (lid & 3) * 2;
#pragma unroll
    for (int mi = 0; mi < 4; ++mi) {
#pragma unroll
        for (int nf = 0; nf < 4; ++nf) {
            int row = m0 + wm * 64 + mi * 16 + r;
            int col = n0 + wn * 32 + nf * 8 + cc;
            float bx = 0.f, by = 0.f;
            if (BIAS) { bx = bias[col]; by = bias[col + 1]; }
            float2 v0 = make_float2(acc[mi][nf][0] + bx, acc[mi][nf][1] + by);
            float2 v1 = make_float2(acc[mi][nf][2] + bx, acc[mi][nf][3] + by);
            *(float2*)(C + (size_t)row * N + col) = v0;
            *(float2*)(C + (size_t)(row + 8) * N + col) = v1;
        }
    }
#undef PREFETCH
}

// ---------------- fp32 -> concat split (GEMM operands) ----------------------
template <int MODE>
__global__ void split_cat_kernel(const float* __restrict__ src,
                                 __nv_bfloat16* __restrict__ dst, int total4) {
    int i = blockIdx.x * blockDim.x + threadIdx.x;
    if (i >= total4) return;
    int row = i >> 7;
    int c4 = i & 127;
    float4 v = ((const float4*)src)[i];
    __nv_bfloat16 h[4], l[4];
    split1(v.x, h[0], l[0]);
    split1(v.y, h[1], l[1]);
    split1(v.z, h[2], l[2]);
    split1(v.w, h[3], l[3]);
    __nv_bfloat16* d = dst + (size_t)row * GKK + c4 * 4;
    if (MODE == 0) {
        *(uint64_t*)(d)        = *(uint64_t*)h;
        *(uint64_t*)(d + 512)  = *(uint64_t*)l;
        *(uint64_t*)(d + 1024) = *(uint64_t*)h;
    } else {
        *(uint64_t*)(d)        = *(uint64_t*)h;
        *(uint64_t*)(d + 512)  = *(uint64_t*)h;
        *(uint64_t*)(d + 1024) = *(uint64_t*)l;
    }
}

// ---------------- RoPE table ------------------------------------------------
__global__ void rope_table_kernel() {
    int idx = blockIdx.x * blockDim.x + threadIdx.x;
    if (idx >= TSEQ * 32) return;
    int t = idx >> 5;
    int j = idx & 31;
    double inv = exp(-log(10000.0) * (double)j / 32.0);
    float ang = (float)t * (float)inv;
    g_cos[idx] = (float)cos((double)ang);
    g_sin[idx] = (float)sin((double)ang);
}

// ---------------- RoPE + split-concat Q/K -----------------------------------
__global__ void rope_qk_kernel() {
    int idx = blockIdx.x * blockDim.x + threadIdx.x;
    const int total = NB * TSEQ * NH * 32;
    if (idx >= total) return;
    int j = idx & 31;
    int h = (idx >> 5) & 7;
    int t = (idx >> 8) & (TSEQ - 1);
    int n = idx >> 19;
    int nh = n * NH + h;

    const float* base = g_qkv + (size_t)(n * TSEQ + t) * EQKV;
    float c = g_cos[t * 32 + j];
    float s = g_sin[t * 32 + j];

    float q1 = base[h * HD + j];
    float q2 = base[h * HD + j + 32];
    float k1 = base[DM + h * HD + j];
    float k2 = base[DM + h * HD + j + 32];

    float q1r = q1 * c - q2 * s;
    float q2r = q2 * c + q1 * s;
    float k1r = k1 * c - k2 * s;
    float k2r = k2 * c + k1 * s;

    __nv_bfloat16 h1, l1, h2, l2;
    __nv_bfloat16* qrow = g_Qc + ((size_t)nh * TSEQ + t) * 192;
    split1(q1r, h1, l1); split1(q2r, h2, l2);
    qrow[j]      = h1; qrow[64 + j] = l1; qrow[128 + j] = h1;
    qrow[32 + j] = h2; qrow[96 + j] = l2; qrow[160 + j] = h2;

    __nv_bfloat16* krow = g_Kc + ((size_t)nh * TSEQ + t) * 192;
    split1(k1r, h1, l1); split1(k2r, h2, l2);
    krow[j]      = h1; krow[64 + j] = h1; krow[128 + j] = l1;
    krow[32 + j] = h2; krow[96 + j] = h2; krow[160 + j] = l2;
}

// ---------------- V transpose + split ---------------------------------------
__global__ void vtrans_kernel() {
    __shared__ __nv_bfloat16 svh[64 * 33];
    __shared__ __nv_bfloat16 svl[64 * 33];
    const int tid = threadIdx.x;
    const int nh = blockIdx.y;
    const int n = nh >> 3, h = nh & 7;
    const int t0 = blockIdx.x * 32;

#pragma unroll
    for (int i = 0; i < 8; i++) {
        int e = tid + i * 256;
        int tl = e >> 6, d = e & 63;
        float v = g_qkv[(size_t)(n * TSEQ + t0 + tl) * EQKV + 2 * DM + h * HD + d];
        __nv_bfloat16 hb, lb;
        split1(v, hb, lb);
        svh[d * 33 + tl] = hb;
        svl[d * 33 + tl] = lb;
    }
    __syncthreads();
#pragma unroll
    for (int i = 0; i < 8; i++) {
        int e = tid + i * 256;
        int d = e >> 5, tl = e & 31;
        size_t o = ((size_t)nh * HD + d) * TSEQ + t0 + tl;
        g_Vth[o] = svh[d * 33 + tl];
        g_Vtl[o] = svl[d * 33 + tl];
    }
}

// ---------------- flash-style banded attention ------------------------------
// CTA per (n*NH+h, 64-q tile). 8 warps: wr = row slice (4), wc = j-half (2).
__global__ __launch_bounds__(256)
void attn_flash_kernel() {
    extern __shared__ char smc[];
    const uint32_t sb = smem_u32(smc);
    float* sRMax = (float*)(smc + ARMAX_OFF);   // [2][64]
    float* sSum  = (float*)(smc + ASUM_OFF);    // [2][64]
    float* sO    = (float*)(smc + AO_OFF);      // [64][64]

    const int tid = threadIdx.x;
    const int lid = tid & 31, wid = tid >> 5;
    const int wr = wid & 3, wc = wid >> 2;
    const int q0 = blockIdx.x * QT;
    const int nh = blockIdx.y;
    const int n = nh >> 3, h = nh & 7;
    const int ks = q0 - 128;
    const float scale = 0.125f;

    const int rlo = wr * 16 + (lid >> 2);
    const int rhi = rlo + 8;

    // ---- Q tile ----
#pragma unroll
    for (int i = 0; i < 6; i++) {
        int u = tid + i * 256;
        int r = u / 24, c = u % 24;
        cp16(sb + AQ_OFF + r * 400 + c * 16,
             g_Qc + ((size_t)nh * TSEQ + q0 + r) * 192 + c * 8);
    }

#define ISSUE_KV(jt_, st_)                                                      \
    {                                                                           \
        _Pragma("unroll")                                                       \
        for (int i = 0; i < 6; i++) {                                           \
            int u = tid + i * 256;                                              \
            int r = u / 24, c = u % 24;                                         \
            int j = ks + (jt_) * 64 + r;                                        \
            j = j < 0 ? 0 : (j > TSEQ - 1 ? TSEQ - 1 : j);                      \
            cp16(sb + AK_OFF(st_) + r * 400 + c * 16,                           \
                 g_Kc + ((size_t)nh * TSEQ + j) * 192 + c * 8);                 \
        }                                                                       \
        _Pragma("unroll")                                                       \
        for (int i = 0; i < 4; i++) {                                           \
            int u = tid + i * 256;                                              \
            int r = u >> 4, c = u & 15;                                         \
            int jb = ks + (jt_) * 64 + (c & 7) * 8;                             \
            jb = jb < 0 ? 0 : (jb > TSEQ - 8 ? TSEQ - 8 : jb);                  \
            const __nv_bfloat16* vs = (c < 8) ? g_Vth : g_Vtl;                  \
            cp16(sb + AV_OFF(st_) + r * 272 + c * 16,                           \
                 vs + ((size_t)nh * HD + r) * TSEQ + jb);                       \
        }                                                                       \
        asm volatile("cp.async.commit_group;" ::: "memory");                    \
    }

    ISSUE_KV(0, 0);

    float oacc[8][4];
#pragma unroll
    for (int i = 0; i < 8; i++)
#pragma unroll
        for (int q = 0; q < 4; q++) oacc[i][q] = 0.f;
    float m0 = -1e30f, m1 = -1e30f;
    float sum0 = 0.f, sum1 = 0.f;   // per-thread partial sums (this thread's cols)

    for (int jt = 0; jt < 5; ++jt) {
        const int st = jt & 1;
        if (jt < 4) {
            ISSUE_KV(jt + 1, st ^ 1);
            asm volatile("cp.async.wait_group 1;" ::: "memory");
        } else {
            asm volatile("cp.async.wait_group 0;" ::: "memory");
        }
        __syncthreads();   // tiles (and for jt=0: Q) visible; prev-stage reads done

        // ---- S = Qcat · Kcat^T (this warp: 16 rows x 32 cols) ----
        float sacc[4][4];
#pragma unroll
        for (int i = 0; i < 4; i++)
#pragma unroll
            for (int q = 0; q < 4; q++) sacc[i][q] = 0.f;

        const uint32_t kb = sb + AK_OFF(st);
#pragma unroll
        for (int k16 = 0; k16 < 12; ++k16) {
            uint32_t a[4], b[2][4];
            {
                int row = wr * 16 + (lid & 7) + ((lid >> 3) & 1) * 8;
                int ke = k16 * 16 + ((lid >> 4) << 3);
                ldsm4(a[0], a[1], a[2], a[3], sb + AQ_OFF + row * 400 + ke * 2);
            }
#pragma unroll
            for (int nb = 0; nb < 2; ++nb) {
                int nn = wc * 32 + nb * 16 + (lid & 7) + ((lid >> 4) & 1) * 8;
                int ke = k16 * 16 + (((lid >> 3) & 1) << 3);
                ldsm4(b[nb][0], b[nb][1], b[nb][2], b[nb][3], kb + nn * 400 + ke * 2);
            }
#pragma unroll
            for (int nf = 0; nf < 4; ++nf)
                mma16816(sacc[nf], a, b[nf >> 1][(nf & 1) * 2],
                         b[nf >> 1][(nf & 1) * 2 + 1]);
        }

        // ---- mask + scale in regs ----
#pragma unroll
        for (int nf = 0; nf < 4; ++nf) {
#pragma unroll
            for (int e = 0; e < 2; ++e) {
                int j = ks + jt * 64 + wc * 32 + nf * 8 + 2 * (lid & 3) + e;
                int d0 = j - (q0 + rlo);
                int d1 = j - (q0 + rhi);
                bool in = (j >= 0) && (j < TSEQ);
                sacc[nf][e]     = (in && d0 >= -127 && d0 <= 128)
                                  ? sacc[nf][e] * scale : -1e30f;
                sacc[nf][2 + e] = (in && d1 >= -127 && d1 <= 128)
                                  ? sacc[nf][2 + e] * scale : -1e30f;
            }
        }

        // ---- online softmax: cross-warp row max ----
        float mx0 = sacc[0][0], mx1 = sacc[0][2];
#pragma unroll
        for (int nf = 0; nf < 4; ++nf) {
            mx0 = fmaxf(mx0, fmaxf(sacc[nf][0], sacc[nf][1]));
            mx1 = fmaxf(mx1, fmaxf(sacc[nf][2], sacc[nf][3]));
        }
        mx0 = fmaxf(mx0, __shfl_xor_sync(0xffffffffu, mx0, 1));
        mx0 = fmaxf(mx0, __shfl_xor_sync(0xffffffffu, mx0, 2));
        mx1 = fmaxf(mx1, __shfl_xor_sync(0xffffffffu, mx1, 1));
        mx1 = fmaxf(mx1, __shfl_xor_sync(0xffffffffu, mx1, 2));
        if ((lid & 3) == 0) {
            sRMax[wc * 64 + rlo] = mx0;
            sRMax[wc * 64 + rhi] = mx1;
        }
        __syncthreads();
        float nm0 = fmaxf(m0, fmaxf(sRMax[rlo], sRMax[64 + rlo]));
        float nm1 = fmaxf(m1, fmaxf(sRMax[rhi], sRMax[64 + rhi]));
        float f0 = __expf(m0 - nm0);
        float f1 = __expf(m1 - nm1);
        m0 = nm0; m1 = nm1;
        sum0 *= f0; sum1 *= f1;
#pragma unroll
        for (int i = 0; i < 8; i++) {
            oacc[i][0] *= f0; oacc[i][1] *= f0;
            oacc[i][2] *= f1; oacc[i][3] *= f1;
        }

        // ---- P = exp(S - m); pack to bf16 hi/lo A-frags ----
        uint32_t ph[2][4], pl[2][4];
#pragma unroll
        for (int nf = 0; nf < 4; ++nf) {
            float p0 = __expf(sacc[nf][0] - nm0);
            float p1 = __expf(sacc[nf][1] - nm0);
            float p2 = __expf(sacc[nf][2] - nm1);
            float p3 = __expf(sacc[nf][3] - nm1);
            sum0 += p0 + p1;
            sum1 += p2 + p3;
            int b = nf >> 1;
            int o = (nf & 1) * 2;  // 0 -> regs a0,a1 ; 1 -> regs a2,a3
            ph[b][o]     = pack2(p0, p1);
            ph[b][o + 1] = pack2(p2, p3);
            pl[b][o]     = pack2lo(p0, p1);
            pl[b][o + 1] = pack2lo(p2, p3);
        }

        // ---- O += Pcat · Vcat (this warp's 32 j-cols; 3-term split) ----
        const uint32_t vb = sb + AV_OFF(st);
#pragma unroll
        for (int b = 0; b < 2; ++b) {
            int kcol = wc * 32 + b * 16;
            uint32_t v[4][4];
#pragma unroll
            for (int dnb = 0; dnb < 4; ++dnb) {
                int nn = dnb * 16 + (lid & 7) + ((lid >> 4) & 1) * 8;
                int kk = kcol + (((lid >> 3) & 1) << 3);
                ldsm4(v[dnb][0], v[dnb][1], v[dnb][2], v[dnb][3],
                      vb + nn * 272 + kk * 2);          // V hi
            }
#pragma unroll
            for (int n8 = 0; n8 < 8; ++n8) {
                mma16816(oacc[n8], ph[b], v[n8 >> 1][(n8 & 1) * 2],
                         v[n8 >> 1][(n8 & 1) * 2 + 1]);
                mma16816(oacc[n8], pl[b], v[n8 >> 1][(n8 & 1) * 2],
                         v[n8 >> 1][(n8 & 1) * 2 + 1]);
            }
#pragma unroll
            for (int dnb = 0; dnb < 4; ++dnb) {
                int nn = dnb * 16 + (lid & 7) + ((lid >> 4) & 1) * 8;
                int kk = kcol + (((lid >> 3) & 1) << 3);
                ldsm4(v[dnb][0], v[dnb][1], v[dnb][2], v[dnb][3],
                      vb + nn * 272 + 128 + kk * 2);    // V lo
            }
#pragma unroll
            for (int n8 = 0; n8 < 8; ++n8)
                mma16816(oacc[n8], ph[b], v[n8 >> 1][(n8 & 1) * 2],
                         v[n8 >> 1][(n8 & 1) * 2 + 1]);
        }
        __syncthreads();   // done reading this stage before its next overwrite
    }
#undef ISSUE_KV

    // ---- combine the two j-half warps, normalize, write split output ----
    sum0 += __shfl_xor_sync(0xffffffffu, sum0, 1);
    sum0 += __shfl_xor_sync(0xffffffffu, sum0, 2);
    sum1 += __shfl_xor_sync(0xffffffffu, sum1, 1);
    sum1 += __shfl_xor_sync(0xffffffffu, sum1, 2);
    if ((lid & 3) == 0) {
        sSum[wc * 64 + rlo] = sum0;
        sSum[wc * 64 + rhi] = sum1;
    }
    if (wc == 1) {
#pragma unroll
        for (int i = 0; i < 8; i++) {
            int d = i * 8 + 2 * (lid & 3);
            sO[rlo * 64 + d] = oacc[i][0];
            sO[rlo * 64 + d + 1] = oacc[i][1];
            sO[rhi * 64 + d] = oacc[i][2];
            sO[rhi * 64 + d + 1] = oacc[i][3];
        }
    }
    __syncthreads();
    if (wc == 0) {
        float inv0 = 1.f / (sSum[rlo] + sSum[64 + rlo]);
        float inv1 = 1.f / (sSum[rhi] + sSum[64 + rhi]);
        __nv_bfloat16* outLo = g_acat + ((size_t)(n * TSEQ) + q0 + rlo) * GKK + h * HD;
        __nv_bfloat16* outHi = g_acat + ((size_t)(n * TSEQ) + q0 + rhi) * GKK + h * HD;
#pragma unroll
        for (int i = 0; i < 8; i++) {
            int d = i * 8 + 2 * (lid & 3);
            float v0 = (oacc[i][0] + sO[rlo * 64 + d]) * inv0;
            float v1 = (oacc[i][1] + sO[rlo * 64 + d + 1]) * inv0;
            float v2 = (oacc[i][2] + sO[rhi * 64 + d]) * inv1;
            float v3 = (oacc[i][3] + sO[rhi * 64 + d + 1]) * inv1;
            uint32_t h01 = pack2(v0, v1), l01 = pack2lo(v0, v1);
            uint32_t h23 = pack2(v2, v3), l23 = pack2lo(v2, v3);
            *(uint32_t*)(outLo + d)        = h01;
            *(uint32_t*)(outLo + d + 512)  = l01;
            *(uint32_t*)(outLo + d + 1024) = h01;
            *(uint32_t*)(outHi + d)        = h23;
            *(uint32_t*)(outHi + d + 512)  = l23;
            *(uint32_t*)(outHi + d + 1024) = h23;
        }
    }
}

// ---------------- launcher ---------------------------------------------------
extern "C" void kernel_launch(void* const* d_in, const int* in_sizes, int n_in,
                              void* d_out, int out_size) {
    (void)in_sizes; (void)n_in; (void)out_size;
    const float* x    = (const float*)d_in[0];
    const float* Wqkv = (const float*)d_in[1];
    const float* Wout = (const float*)d_in[2];
    const float* bout = (const float*)d_in[3];
    float* out = (float*)d_out;

    float* qkv_ptr = nullptr;
    cudaGetSymbolAddress((void**)&qkv_ptr, g_qkv);
    __nv_bfloat16 *xcat, *acat, *wqcat, *wocat;
    cudaGetSymbolAddress((void**)&xcat, g_xcat);
    cudaGetSymbolAddress((void**)&acat, g_acat);
    cudaGetSymbolAddress((void**)&wqcat, g_wqcat);
    cudaGetSymbolAddress((void**)&wocat, g_wocat);

    cudaFuncSetAttribute(attn_flash_kernel,
                         cudaFuncAttributeMaxDynamicSharedMemorySize,
                         AFL_SMEM);

    rope_table_kernel<<<(TSEQ * 32 + 255) / 256, 256>>>();

    split_cat_kernel<0><<<(MTOT * 128 + 255) / 256, 256>>>(x, xcat, MTOT * 128);
    split_cat_kernel<1><<<(EQKV * 128 + 255) / 256, 256>>>(Wqkv, wqcat, EQKV * 128);
    split_cat_kernel<1><<<(DM * 128 + 255) / 256, 256>>>(Wout, wocat, DM * 128);

    // qkv = x @ Wqkv^T  (split-bf16 HMMA, K=1536)
    gemm_mma<false><<<dim3(EQKV / 128, MTOT / 128), 256>>>(
        xcat, wqcat, nullptr, qkv_ptr, EQKV);

    rope_qk_kernel<<<(NB * TSEQ * NH * 32 + 255) / 256, 256>>>();
    vtrans_kernel<<<dim3(TSEQ / 32, NB * NH), 256>>>();

    // attention writes split-concat output (acat) directly
    attn_flash_kernel<<<dim3(TSEQ / QT, NB * NH), 256, AFL_SMEM>>>();

    // out = attn @ Wout^T + bout
    gemm_mma<true><<<dim3(DM / 128, MTOT / 128), 256>>>(
        acat, wocat, bout, out, DM);
}

// round 9
// speedup vs baseline: 2.1445x; 1.0465x over previous
#include <cuda_runtime.h>
#include <cuda_bf16.h>
#include <math.h>
#include <stdint.h>

#define NB 8
#define TSEQ 2048
#define DM 512
#define NH 8
#define HD 64
#define MTOT (NB * TSEQ)          // 16384
#define EQKV (3 * DM)             // 1536
#define GKK 1536                  // concatenated K = 3 * 512

#define QT 64

// ---- flash attention smem layout (bytes) ----
#define AQ_OFF   0                         // 64 x 200 bf16 (Qcat), pitch 400B
#define AK_OFF(s) (25600 + (s) * 43008)    // 64 x 200 bf16 K tile, pitch 400B
#define AV_OFF(s) (AK_OFF(s) + 25600)      // 64 x 136 bf16 V tile (hi|lo), pitch 272B
#define ARMAX_OFF 111616                   // 2 x 64 fp32
#define ASUM_OFF  112128                   // 2 x 64 fp32
#define AO_OFF    25600                    // 64 x 64 fp32 exchange (overlays stage0 K)
#define AFL_SMEM  112640

// ---------------- scratch (device globals) ----------------------------------
__device__ float g_qkv[(size_t)MTOT * EQKV];
__device__ float g_cos[TSEQ * 32];
__device__ float g_sin[TSEQ * 32];
__device__ __nv_bfloat16 g_Qc[(size_t)NB * NH * TSEQ * 192];  // [Qh|Ql|Qh]
__device__ __nv_bfloat16 g_Kc[(size_t)NB * NH * TSEQ * 192];  // [Kh|Kh|Kl]
__device__ __nv_bfloat16 g_Vth[(size_t)NB * NH * HD * TSEQ];  // V^T hi [d][t]
__device__ __nv_bfloat16 g_Vtl[(size_t)NB * NH * HD * TSEQ];  // V^T lo [d][t]
__device__ __nv_bfloat16 g_xcat[(size_t)MTOT * GKK];
__device__ __nv_bfloat16 g_acat[(size_t)MTOT * GKK];          // attention out (split)
__device__ __nv_bfloat16 g_wqcat[(size_t)EQKV * GKK];
__device__ __nv_bfloat16 g_wocat[(size_t)DM * GKK];

// ---------------- helpers ----------------------------------------------------
__device__ __forceinline__ uint32_t smem_u32(const void* p) {
    uint32_t a;
    asm("{ .reg .u64 t; cvta.to.shared.u64 t, %1; cvt.u32.u64 %0, t; }"
        : "=r"(a) : "l"(p));
    return a;
}

__device__ __forceinline__ void cp16(uint32_t dst, const void* src) {
    asm volatile("cp.async.cg.shared.global [%0], [%1], 16;"
                 :: "r"(dst), "l"(src) : "memory");
}

__device__ __forceinline__ void ldsm4(uint32_t& r0, uint32_t& r1,
                                      uint32_t& r2, uint32_t& r3, uint32_t addr) {
    asm volatile("ldmatrix.sync.aligned.m8n8.x4.shared.b16 {%0,%1,%2,%3}, [%4];"
                 : "=r"(r0), "=r"(r1), "=r"(r2), "=r"(r3) : "r"(addr));
}

__device__ __forceinline__ void mma16816(float* c, const uint32_t* a,
                                         uint32_t b0, uint32_t b1) {
    asm volatile(
        "mma.sync.aligned.m16n8k16.row.col.f32.bf16.bf16.f32 "
        "{%0,%1,%2,%3}, {%4,%5,%6,%7}, {%8,%9}, {%0,%1,%2,%3};"
        : "+f"(c[0]), "+f"(c[1]), "+f"(c[2]), "+f"(c[3])
        : "r"(a[0]), "r"(a[1]), "r"(a[2]), "r"(a[3]), "r"(b0), "r"(b1));
}

__device__ __forceinline__ void split1(float x, __nv_bfloat16& h, __nv_bfloat16& l) {
    h = __float2bfloat16(x);
    l = __float2bfloat16(x - __bfloat162float(h));
}

__device__ __forceinline__ uint16_t bfbits(__nv_bfloat16 b) {
    return *reinterpret_cast<uint16_t*>(&b);
}

__device__ __forceinline__ uint32_t pack2(float a, float b) {
    __nv_bfloat16 ha = __float2bfloat16(a), hb = __float2bfloat16(b);
    return (uint32_t)bfbits(ha) | ((uint32_t)bfbits(hb) << 16);
}

// pack the bf16 lo-residuals of a,b
__device__ __forceinline__ uint32_t pack2lo(float a, float b) {
    __nv_bfloat16 ha = __float2bfloat16(a), hb = __float2bfloat16(b);
    __nv_bfloat16 la = __float2bfloat16(a - __bfloat162float(ha));
    __nv_bfloat16 lb = __float2bfloat16(b - __bfloat162float(hb));
    return (uint32_t)bfbits(la) | ((uint32_t)bfbits(lb) << 16);
}

// ---------------- bf16 mma.sync GEMM (3-stage pipeline, occ 2) --------------
#define SROW 40
#define STAGE_BYTES (128 * SROW * 2)   // 10240

template <bool BIAS>
__global__ __launch_bounds__(256, 2)
void gemm_mma(const __nv_bfloat16* __restrict__ A, const __nv_bfloat16* __restrict__ B,
              const float* __restrict__ bias, float* __restrict__ C, int N) {
    __shared__ __nv_bfloat16 sA[3][128 * SROW];
    __shared__ __nv_bfloat16 sB[3][128 * SROW];

    const int tid = threadIdx.x;
    const int lid = tid & 31;
    const int wid = tid >> 5;
    const int wm = wid >> 2;
    const int wn = wid & 3;
    const int m0 = blockIdx.y * 128;
    const int n0 = blockIdx.x * 128;
    const uint32_t sAb = smem_u32(sA);
    const uint32_t sBb = smem_u32(sB);

    float acc[4][4][4];
#pragma unroll
    for (int i = 0; i < 4; i++)
#pragma unroll
        for (int j = 0; j < 4; j++)
#pragma unroll
            for (int q = 0; q < 4; q++) acc[i][j][q] = 0.f;

#define PREFETCH(stage, k0)                                                     \
    {                                                                           \
        _Pragma("unroll")                                                       \
        for (int i = 0; i < 2; ++i) {                                           \
            int u = tid + i * 256;                                              \
            int row = u >> 2, c = u & 3;                                        \
            cp16(sAb + (stage) * STAGE_BYTES + row * 80 + c * 16,               \
                 A + (size_t)(m0 + row) * GKK + (k0) + c * 8);                  \
            cp16(sBb + (stage) * STAGE_BYTES + row * 80 + c * 16,               \
                 B + (size_t)(n0 + row) * GKK + (k0) + c * 8);                  \
        }                                                                       \
        asm volatile("cp.async.commit_group;" ::: "memory");                    \
    }

    const int NKT = GKK / 32;   // 48
    PREFETCH(0, 0);
    PREFETCH(1, 32);

    int stage = 0;
    for (int kt = 0; kt < NKT; ++kt) {
        if (kt + 2 < NKT) {
            int ps = stage + 2; if (ps >= 3) ps -= 3;
            PREFETCH(ps, (kt + 2) * 32);
            asm volatile("cp.async.wait_group 2;" ::: "memory");
        } else if (kt + 1 < NKT) {
            asm volatile("cp.async.wait_group 1;" ::: "memory");
        } else {
            asm volatile("cp.async.wait_group 0;" ::: "memory");
        }
        __syncthreads();

        const uint32_t sa = sAb + stage * STAGE_BYTES;
        const uint32_t sb = sBb + stage * STAGE_BYTES;

#pragma unroll
        for (int ks = 0; ks < 32; ks += 16) {
            uint32_t a[4][4], b[2][4];
#pragma unroll
            for (int mi = 0; mi < 4; ++mi) {
                int row = wm * 64 + mi * 16 + (lid & 7) + ((lid >> 3) & 1) * 8;
                int ke = ks + ((lid >> 4) << 3);
                ldsm4(a[mi][0], a[mi][1], a[mi][2], a[mi][3],
                      sa + (uint32_t)(row * SROW + ke) * 2);
            }
#pragma unroll
            for (int nb = 0; nb < 2; ++nb) {
                int n = wn * 32 + nb * 16 + (lid & 7) + ((lid >> 4) & 1) * 8;
                int ke = ks + (((lid >> 3) & 1) << 3);
                ldsm4(b[nb][0], b[nb][1], b[nb][2], b[nb][3],
                      sb + (uint32_t)(n * SROW + ke) * 2);
            }
#pragma unroll
            for (int mi = 0; mi < 4; ++mi)
#pragma unroll
                for (int nf = 0; nf < 4; ++nf)
                    mma16816(acc[mi][nf], a[mi],
                             b[nf >> 1][(nf & 1) * 2], b[nf >> 1][(nf & 1) * 2 + 1]);
        }
        __syncthreads();
        ++stage; if (stage == 3) stage = 0;
    }

    const int r = lid >> 2;
    const int cc = (lid & 3) * 2;
#pragma unroll
    for (int mi = 0; mi < 4; ++mi) {
#pragma unroll
        for (int nf = 0; nf < 4; ++nf) {
            int row = m0 + wm * 64 + mi * 16 + r;
            int col = n0 + wn * 32 + nf * 8 + cc;
            float bx = 0.f, by = 0.f;
            if (BIAS) { bx = bias[col]; by = bias[col + 1]; }
            float2 v0 = make_float2(acc[mi][nf][0] + bx, acc[mi][nf][1] + by);
            float2 v1 = make_float2(acc[mi][nf][2] + bx, acc[mi][nf][3] + by);
            *(float2*)(C + (size_t)row * N + col) = v0;
            *(float2*)(C + (size_t)(row + 8) * N + col) = v1;
        }
    }
#undef PREFETCH
}

// ---------------- fp32 -> concat split (GEMM operands) ----------------------
template <int MODE>
__global__ void split_cat_kernel(const float* __restrict__ src,
                                 __nv_bfloat16* __restrict__ dst, int total4) {
    int i = blockIdx.x * blockDim.x + threadIdx.x;
    if (i >= total4) return;
    int row = i >> 7;
    int c4 = i & 127;
    float4 v = ((const float4*)src)[i];
    __nv_bfloat16 h[4], l[4];
    split1(v.x, h[0], l[0]);
    split1(v.y, h[1], l[1]);
    split1(v.z, h[2], l[2]);
    split1(v.w, h[3], l[3]);
    __nv_bfloat16* d = dst + (size_t)row * GKK + c4 * 4;
    if (MODE == 0) {
        *(uint64_t*)(d)        = *(uint64_t*)h;
        *(uint64_t*)(d + 512)  = *(uint64_t*)l;
        *(uint64_t*)(d + 1024) = *(uint64_t*)h;
    } else {
        *(uint64_t*)(d)        = *(uint64_t*)h;
        *(uint64_t*)(d + 512)  = *(uint64_t*)h;
        *(uint64_t*)(d + 1024) = *(uint64_t*)l;
    }
}

// ---------------- RoPE table ------------------------------------------------
__global__ void rope_table_kernel() {
    int idx = blockIdx.x * blockDim.x + threadIdx.x;
    if (idx >= TSEQ * 32) return;
    int t = idx >> 5;
    int j = idx & 31;
    double inv = exp(-log(10000.0) * (double)j / 32.0);
    float ang = (float)t * (float)inv;
    g_cos[idx] = (float)cos((double)ang);
    g_sin[idx] = (float)sin((double)ang);
}

// ---------------- RoPE + split-concat Q/K -----------------------------------
__global__ void rope_qk_kernel() {
    int idx = blockIdx.x * blockDim.x + threadIdx.x;
    const int total = NB * TSEQ * NH * 32;
    if (idx >= total) return;
    int j = idx & 31;
    int h = (idx >> 5) & 7;
    int t = (idx >> 8) & (TSEQ - 1);
    int n = idx >> 19;
    int nh = n * NH + h;

    const float* base = g_qkv + (size_t)(n * TSEQ + t) * EQKV;
    float c = g_cos[t * 32 + j];
    float s = g_sin[t * 32 + j];

    float q1 = base[h * HD + j];
    float q2 = base[h * HD + j + 32];
    float k1 = base[DM + h * HD + j];
    float k2 = base[DM + h * HD + j + 32];

    float q1r = q1 * c - q2 * s;
    float q2r = q2 * c + q1 * s;
    float k1r = k1 * c - k2 * s;
    float k2r = k2 * c + k1 * s;

    __nv_bfloat16 h1, l1, h2, l2;
    __nv_bfloat16* qrow = g_Qc + ((size_t)nh * TSEQ + t) * 192;
    split1(q1r, h1, l1); split1(q2r, h2, l2);
    qrow[j]      = h1; qrow[64 + j] = l1; qrow[128 + j] = h1;
    qrow[32 + j] = h2; qrow[96 + j] = l2; qrow[160 + j] = h2;

    __nv_bfloat16* krow = g_Kc + ((size_t)nh * TSEQ + t) * 192;
    split1(k1r, h1, l1); split1(k2r, h2, l2);
    krow[j]      = h1; krow[64 + j] = h1; krow[128 + j] = l1;
    krow[32 + j] = h2; krow[96 + j] = h2; krow[160 + j] = l2;
}

// ---------------- V transpose + split ---------------------------------------
__global__ void vtrans_kernel() {
    __shared__ __nv_bfloat16 svh[64 * 33];
    __shared__ __nv_bfloat16 svl[64 * 33];
    const int tid = threadIdx.x;
    const int nh = blockIdx.y;
    const int n = nh >> 3, h = nh & 7;
    const int t0 = blockIdx.x * 32;

#pragma unroll
    for (int i = 0; i < 8; i++) {
        int e = tid + i * 256;
        int tl = e >> 6, d = e & 63;
        float v = g_qkv[(size_t)(n * TSEQ + t0 + tl) * EQKV + 2 * DM + h * HD + d];
        __nv_bfloat16 hb, lb;
        split1(v, hb, lb);
        svh[d * 33 + tl] = hb;
        svl[d * 33 + tl] = lb;
    }
    __syncthreads();
#pragma unroll
    for (int i = 0; i < 8; i++) {
        int e = tid + i * 256;
        int d = e >> 5, tl = e & 31;
        size_t o = ((size_t)nh * HD + d) * TSEQ + t0 + tl;
        g_Vth[o] = svh[d * 33 + tl];
        g_Vtl[o] = svl[d * 33 + tl];
    }
}

// ---------------- flash-style banded attention ------------------------------
// CTA per (n*NH+h, 64-q tile). 8 warps: wr = row slice (4), wc = j-half (2).
__global__ __launch_bounds__(256, 2)
void attn_flash_kernel() {
    extern __shared__ char smc[];
    const uint32_t sb = smem_u32(smc);
    float* sRMax = (float*)(smc + ARMAX_OFF);   // [2][64]
    float* sSum  = (float*)(smc + ASUM_OFF);    // [2][64]
    float* sO    = (float*)(smc + AO_OFF);      // [64][64]

    const int tid = threadIdx.x;
    const int lid = tid & 31, wid = tid >> 5;
    const int wr = wid & 3, wc = wid >> 2;
    const int q0 = blockIdx.x * QT;
    const int nh = blockIdx.y;
    const int n = nh >> 3, h = nh & 7;
    const int ks = q0 - 128;
    const float scale = 0.125f;

    const int rlo = wr * 16 + (lid >> 2);
    const int rhi = rlo + 8;

    // ---- Q tile ----
#pragma unroll
    for (int i = 0; i < 6; i++) {
        int u = tid + i * 256;
        int r = u / 24, c = u % 24;
        cp16(sb + AQ_OFF + r * 400 + c * 16,
             g_Qc + ((size_t)nh * TSEQ + q0 + r) * 192 + c * 8);
    }

#define ISSUE_KV(jt_, st_)                                                      \
    {                                                                           \
        _Pragma("unroll")                                                       \
        for (int i = 0; i < 6; i++) {                                           \
            int u = tid + i * 256;                                              \
            int r = u / 24, c = u % 24;                                         \
            int j = ks + (jt_) * 64 + r;                                        \
            j = j < 0 ? 0 : (j > TSEQ - 1 ? TSEQ - 1 : j);                      \
            cp16(sb + AK_OFF(st_) + r * 400 + c * 16,                           \
                 g_Kc + ((size_t)nh * TSEQ + j) * 192 + c * 8);                 \
        }                                                                       \
        _Pragma("unroll")                                                       \
        for (int i = 0; i < 4; i++) {                                           \
            int u = tid + i * 256;                                              \
            int r = u >> 4, c = u & 15;                                         \
            int jb = ks + (jt_) * 64 + (c & 7) * 8;                             \
            jb = jb < 0 ? 0 : (jb > TSEQ - 8 ? TSEQ - 8 : jb);                  \
            const __nv_bfloat16* vs = (c < 8) ? g_Vth : g_Vtl;                  \
            cp16(sb + AV_OFF(st_) + r * 272 + c * 16,                           \
                 vs + ((size_t)nh * HD + r) * TSEQ + jb);                       \
        }                                                                       \
        asm volatile("cp.async.commit_group;" ::: "memory");                    \
    }

    ISSUE_KV(0, 0);

    float oacc[8][4];
#pragma unroll
    for (int i = 0; i < 8; i++)
#pragma unroll
        for (int q = 0; q < 4; q++) oacc[i][q] = 0.f;
    float m0 = -1e30f, m1 = -1e30f;
    float sum0 = 0.f, sum1 = 0.f;   // per-thread partial sums (this thread's cols)

    for (int jt = 0; jt < 5; ++jt) {
        const int st = jt & 1;
        if (jt < 4) {
            ISSUE_KV(jt + 1, st ^ 1);
            asm volatile("cp.async.wait_group 1;" ::: "memory");
        } else {
            asm volatile("cp.async.wait_group 0;" ::: "memory");
        }
        __syncthreads();   // tiles (and for jt=0: Q) visible; prev-stage reads done

        // ---- S = Qcat · Kcat^T (this warp: 16 rows x 32 cols) ----
        float sacc[4][4];
#pragma unroll
        for (int i = 0; i < 4; i++)
#pragma unroll
            for (int q = 0; q < 4; q++) sacc[i][q] = 0.f;

        const uint32_t kb = sb + AK_OFF(st);
#pragma unroll
        for (int k16 = 0; k16 < 12; ++k16) {
            uint32_t a[4], b[2][4];
            {
                int row = wr * 16 + (lid & 7) + ((lid >> 3) & 1) * 8;
                int ke = k16 * 16 + ((lid >> 4) << 3);
                ldsm4(a[0], a[1], a[2], a[3], sb + AQ_OFF + row * 400 + ke * 2);
            }
#pragma unroll
            for (int nb = 0; nb < 2; ++nb) {
                int nn = wc * 32 + nb * 16 + (lid & 7) + ((lid >> 4) & 1) * 8;
                int ke = k16 * 16 + (((lid >> 3) & 1) << 3);
                ldsm4(b[nb][0], b[nb][1], b[nb][2], b[nb][3], kb + nn * 400 + ke * 2);
            }
#pragma unroll
            for (int nf = 0; nf < 4; ++nf)
                mma16816(sacc[nf], a, b[nf >> 1][(nf & 1) * 2],
                         b[nf >> 1][(nf & 1) * 2 + 1]);
        }

        // ---- mask + scale in regs ----
#pragma unroll
        for (int nf = 0; nf < 4; ++nf) {
#pragma unroll
            for (int e = 0; e < 2; ++e) {
                int j = ks + jt * 64 + wc * 32 + nf * 8 + 2 * (lid & 3) + e;
                int d0 = j - (q0 + rlo);
                int d1 = j - (q0 + rhi);
                bool in = (j >= 0) && (j < TSEQ);
                sacc[nf][e]     = (in && d0 >= -127 && d0 <= 128)
                                  ? sacc[nf][e] * scale : -1e30f;
                sacc[nf][2 + e] = (in && d1 >= -127 && d1 <= 128)
                                  ? sacc[nf][2 + e] * scale : -1e30f;
            }
        }

        // ---- online softmax: cross-warp row max ----
        float mx0 = sacc[0][0], mx1 = sacc[0][2];
#pragma unroll
        for (int nf = 0; nf < 4; ++nf) {
            mx0 = fmaxf(mx0, fmaxf(sacc[nf][0], sacc[nf][1]));
            mx1 = fmaxf(mx1, fmaxf(sacc[nf][2], sacc[nf][3]));
        }
        mx0 = fmaxf(mx0, __shfl_xor_sync(0xffffffffu, mx0, 1));
        mx0 = fmaxf(mx0, __shfl_xor_sync(0xffffffffu, mx0, 2));
        mx1 = fmaxf(mx1, __shfl_xor_sync(0xffffffffu, mx1, 1));
        mx1 = fmaxf(mx1, __shfl_xor_sync(0xffffffffu, mx1, 2));
        if ((lid & 3) == 0) {
            sRMax[wc * 64 + rlo] = mx0;
            sRMax[wc * 64 + rhi] = mx1;
        }
        __syncthreads();
        float nm0 = fmaxf(m0, fmaxf(sRMax[rlo], sRMax[64 + rlo]));
        float nm1 = fmaxf(m1, fmaxf(sRMax[rhi], sRMax[64 + rhi]));
        float f0 = __expf(m0 - nm0);
        float f1 = __expf(m1 - nm1);
        m0 = nm0; m1 = nm1;
        sum0 *= f0; sum1 *= f1;
#pragma unroll
        for (int i = 0; i < 8; i++) {
            oacc[i][0] *= f0; oacc[i][1] *= f0;
            oacc[i][2] *= f1; oacc[i][3] *= f1;
        }

        // ---- P = exp(S - m); pack to bf16 hi/lo A-frags ----
        uint32_t ph[2][4], pl[2][4];
#pragma unroll
        for (int nf = 0; nf < 4; ++nf) {
            float p0 = __expf(sacc[nf][0] - nm0);
            float p1 = __expf(sacc[nf][1] - nm0);
            float p2 = __expf(sacc[nf][2] - nm1);
            float p3 = __expf(sacc[nf][3] - nm1);
            sum0 += p0 + p1;
            sum1 += p2 + p3;
            int b = nf >> 1;
            int o = (nf & 1) * 2;  // 0 -> regs a0,a1 ; 1 -> regs a2,a3
            ph[b][o]     = pack2(p0, p1);
            ph[b][o + 1] = pack2(p2, p3);
            pl[b][o]     = pack2lo(p0, p1);
            pl[b][o + 1] = pack2lo(p2, p3);
        }

        // ---- O += Pcat · Vcat (this warp's 32 j-cols; 3-term split) ----
        const uint32_t vb = sb + AV_OFF(st);
#pragma unroll
        for (int b = 0; b < 2; ++b) {
            int kcol = wc * 32 + b * 16;
            uint32_t v[4][4];
#pragma unroll
            for (int dnb = 0; dnb < 4; ++dnb) {
                int nn = dnb * 16 + (lid & 7) + ((lid >> 4) & 1) * 8;
                int kk = kcol + (((lid >> 3) & 1) << 3);
                ldsm4(v[dnb][0], v[dnb][1], v[dnb][2], v[dnb][3],
                      vb + nn * 272 + kk * 2);          // V hi
            }
#pragma unroll
            for (int n8 = 0; n8 < 8; ++n8) {
                mma16816(oacc[n8], ph[b], v[n8 >> 1][(n8 & 1) * 2],
                         v[n8 >> 1][(n8 & 1) * 2 + 1]);
                mma16816(oacc[n8], pl[b], v[n8 >> 1][(n8 & 1) * 2],
                         v[n8 >> 1][(n8 & 1) * 2 + 1]);
            }
#pragma unroll
            for (int dnb = 0; dnb < 4; ++dnb) {
                int nn = dnb * 16 + (lid & 7) + ((lid >> 4) & 1) * 8;
                int kk = kcol + (((lid >> 3) & 1) << 3);
                ldsm4(v[dnb][0], v[dnb][1], v[dnb][2], v[dnb][3],
                      vb + nn * 272 + 128 + kk * 2);    // V lo
            }
#pragma unroll
            for (int n8 = 0; n8 < 8; ++n8)
                mma16816(oacc[n8], ph[b], v[n8 >> 1][(n8 & 1) * 2],
                         v[n8 >> 1][(n8 & 1) * 2 + 1]);
        }
        __syncthreads();   // done reading this stage before its next overwrite
    }
#undef ISSUE_KV

    // ---- combine the two j-half warps, normalize, write split output ----
    sum0 += __shfl_xor_sync(0xffffffffu, sum0, 1);
    sum0 += __shfl_xor_sync(0xffffffffu, sum0, 2);
    sum1 += __shfl_xor_sync(0xffffffffu, sum1, 1);
    sum1 += __shfl_xor_sync(0xffffffffu, sum1, 2);
    if ((lid & 3) == 0) {
        sSum[wc * 64 + rlo] = sum0;
        sSum[wc * 64 + rhi] = sum1;
    }
    if (wc == 1) {
#pragma unroll
        for (int i = 0; i < 8; i++) {
            int d = i * 8 + 2 * (lid & 3);
            sO[rlo * 64 + d] = oacc[i][0];
            sO[rlo * 64 + d + 1] = oacc[i][1];
            sO[rhi * 64 + d] = oacc[i][2];
            sO[rhi * 64 + d + 1] = oacc[i][3];
        }
    }
    __syncthreads();
    if (wc == 0) {
        float inv0 = 1.f / (sSum[rlo] + sSum[64 + rlo]);
        float inv1 = 1.f / (sSum[rhi] + sSum[64 + rhi]);
        __nv_bfloat16* outLo = g_acat + ((size_t)(n * TSEQ) + q0 + rlo) * GKK + h * HD;
        __nv_bfloat16* outHi = g_acat + ((size_t)(n * TSEQ) + q0 + rhi) * GKK + h * HD;
#pragma unroll
        for (int i = 0; i < 8; i++) {
            int d = i * 8 + 2 * (lid & 3);
            float v0 = (oacc[i][0] + sO[rlo * 64 + d]) * inv0;
            float v1 = (oacc[i][1] + sO[rlo * 64 + d + 1]) * inv0;
            float v2 = (oacc[i][2] + sO[rhi * 64 + d]) * inv1;
            float v3 = (oacc[i][3] + sO[rhi * 64 + d + 1]) * inv1;
            uint32_t h01 = pack2(v0, v1), l01 = pack2lo(v0, v1);
            uint32_t h23 = pack2(v2, v3), l23 = pack2lo(v2, v3);
            *(uint32_t*)(outLo + d)        = h01;
            *(uint32_t*)(outLo + d + 512)  = l01;
            *(uint32_t*)(outLo + d + 1024) = h01;
            *(uint32_t*)(outHi + d)        = h23;
            *(uint32_t*)(outHi + d + 512)  = l23;
            *(uint32_t*)(outHi + d + 1024) = h23;
        }
    }
}

// ---------------- launcher ---------------------------------------------------
extern "C" void kernel_launch(void* const* d_in, const int* in_sizes, int n_in,
                              void* d_out, int out_size) {
    (void)in_sizes; (void)n_in; (void)out_size;
    const float* x    = (const float*)d_in[0];
    const float* Wqkv = (const float*)d_in[1];
    const float* Wout = (const float*)d_in[2];
    const float* bout = (const float*)d_in[3];
    float* out = (float*)d_out;

    float* qkv_ptr = nullptr;
    cudaGetSymbolAddress((void**)&qkv_ptr, g_qkv);
    __nv_bfloat16 *xcat, *acat, *wqcat, *wocat;
    cudaGetSymbolAddress((void**)&xcat, g_xcat);
    cudaGetSymbolAddress((void**)&acat, g_acat);
    cudaGetSymbolAddress((void**)&wqcat, g_wqcat);
    cudaGetSymbolAddress((void**)&wocat, g_wocat);

    cudaFuncSetAttribute(attn_flash_kernel,
                         cudaFuncAttributeMaxDynamicSharedMemorySize,
                         AFL_SMEM);

    rope_table_kernel<<<(TSEQ * 32 + 255) / 256, 256>>>();

    split_cat_kernel<0><<<(MTOT * 128 + 255) / 256, 256>>>(x, xcat, MTOT * 128);
    split_cat_kernel<1><<<(EQKV * 128 + 255) / 256, 256>>>(Wqkv, wqcat, EQKV * 128);
    split_cat_kernel<1><<<(DM * 128 + 255) / 256, 256>>>(Wout, wocat, DM * 128);

    // qkv = x @ Wqkv^T  (split-bf16 HMMA, K=1536)
    gemm_mma<false><<<dim3(EQKV / 128, MTOT / 128), 256>>>(
        xcat, wqcat, nullptr, qkv_ptr, EQKV);

    rope_qk_kernel<<<(NB * TSEQ * NH * 32 + 255) / 256, 256>>>();
    vtrans_kernel<<<dim3(TSEQ / 32, NB * NH), 256>>>();

    // attention writes split-concat output (acat) directly
    attn_flash_kernel<<<dim3(TSEQ / QT, NB * NH), 256, AFL_SMEM>>>();

    // out = attn @ Wout^T + bout
    gemm_mma<true><<<dim3(DM / 128, MTOT / 128), 256>>>(
        acat, wocat, bout, out, DM);
}